// round 11
// baseline (speedup 1.0000x reference)
#include <cuda_runtime.h>
#include <cuda_bf16.h>
#include <cstdint>

#define BATCH   4
#define SEQ     2048
#define DIN     1024
#define NH      16
#define DE      64
#define MROWS   (BATCH * SEQ)   // 8192

// ---------------------------------------------------------------------------
// Device scratch (static — no allocation).
// ---------------------------------------------------------------------------
__device__ float g_q[BATCH * NH * SEQ * DE];
__device__ float g_k[BATCH * NH * SEQ * DE];
__device__ float g_v[BATCH * NH * SEQ * DE];

__device__ __align__(16) __nv_bfloat16 g_xhi[MROWS * DIN];
__device__ __align__(16) __nv_bfloat16 g_xlo[MROWS * DIN];
// W transposed+split: [z][h][e][k], k contiguous (1024)
__device__ __align__(16) __nv_bfloat16 g_wthi[3 * NH * DE * DIN];
__device__ __align__(16) __nv_bfloat16 g_wtlo[3 * NH * DE * DIN];

// ---------------------------------------------------------------------------
// Warp-level MMA helpers (baseline PTX — works on sm_100 non-'a' target).
// ---------------------------------------------------------------------------
__device__ __forceinline__ uint32_t smem_to_u32(const void* p) {
    uint32_t a;
    asm("{ .reg .u64 t; cvta.to.shared.u64 t, %1; cvt.u32.u64 %0, t; }" : "=r"(a) : "l"(p));
    return a;
}
__device__ __forceinline__ void ldsm_x4(uint32_t* r, uint32_t addr) {
    asm volatile("ldmatrix.sync.aligned.m8n8.x4.shared.b16 {%0,%1,%2,%3}, [%4];"
                 : "=r"(r[0]), "=r"(r[1]), "=r"(r[2]), "=r"(r[3]) : "r"(addr));
}
__device__ __forceinline__ void mma_bf16(float* c, const uint32_t* a, const uint32_t* b) {
    asm volatile("mma.sync.aligned.m16n8k16.row.col.f32.bf16.bf16.f32 "
                 "{%0,%1,%2,%3}, {%4,%5,%6,%7}, {%8,%9}, {%0,%1,%2,%3};"
                 : "+f"(c[0]), "+f"(c[1]), "+f"(c[2]), "+f"(c[3])
                 : "r"(a[0]), "r"(a[1]), "r"(a[2]), "r"(a[3]), "r"(b[0]), "r"(b[1]));
}
#define SMEM_SWIZZLE_128B(o) ((o) ^ (((o) >> 3) & 0x70))

// ---------------------------------------------------------------------------
// Fast exp on the FMA/ALU pipes (no MUFU). exp(t) for t <= ~0.
// x = t*log2e clamped to >= -120; 2^frac via degree-5 Taylor (rel err < 8e-5);
// 2^floor via exponent bit construction. Masked t=-1e30 -> ~2^-120 ~ 0.
// ---------------------------------------------------------------------------
__device__ __forceinline__ float fast_exp(float t) {
    float x = t * 1.4426950408889634f;
    x = fmaxf(x, -120.0f);
    float fl = floorf(x);
    float f = x - fl;
    float p = 0.0013333558f;
    p = fmaf(p, f, 0.0096181291f);
    p = fmaf(p, f, 0.0555041086f);
    p = fmaf(p, f, 0.2402265069f);
    p = fmaf(p, f, 0.6931471806f);
    p = fmaf(p, f, 1.0f);
    const int i = (int)fl;
    const float sc = __int_as_float((i + 127) << 23);
    return p * sc;
}

// ---------------------------------------------------------------------------
// Convert X -> bf16 hi/lo (same [m][k] layout).
// ---------------------------------------------------------------------------
__global__ __launch_bounds__(256) void convert_x_kernel(const float* __restrict__ X) {
    const int i = blockIdx.x * 256 + threadIdx.x;   // float4 index
    float4 v = ((const float4*)X)[i];
    float xs[4] = {v.x, v.y, v.z, v.w};
    union { __nv_bfloat16 h[4]; uint2 u; } hi, lo;
#pragma unroll
    for (int j = 0; j < 4; j++) {
        __nv_bfloat16 h = __float2bfloat16(xs[j]);
        hi.h[j] = h;
        lo.h[j] = __float2bfloat16(xs[j] - __bfloat162float(h));
    }
    ((uint2*)g_xhi)[i] = hi.u;
    ((uint2*)g_xlo)[i] = lo.u;
}

// ---------------------------------------------------------------------------
// Convert + transpose W: [z][h][k][e] fp32 -> [z][h][e][k] bf16 hi/lo.
// ---------------------------------------------------------------------------
__global__ __launch_bounds__(256) void convert_w_kernel(
    const float* __restrict__ Wq, const float* __restrict__ Wk, const float* __restrict__ Wv) {
    const int zh = blockIdx.x;
    const int z = zh / NH, h = zh % NH;
    const float* __restrict__ W = (z == 0) ? Wq : (z == 1) ? Wk : Wv;
    const float* __restrict__ Wh = W + (size_t)h * DIN * DE;
    __nv_bfloat16* __restrict__ oh = g_wthi + (size_t)zh * DE * DIN;
    __nv_bfloat16* __restrict__ ol = g_wtlo + (size_t)zh * DE * DIN;
    for (int j = threadIdx.x; j < DE * DIN; j += 256) {
        const int e = j / DIN, k = j % DIN;
        const float x = Wh[(size_t)k * DE + e];
        const __nv_bfloat16 hb = __float2bfloat16(x);
        oh[j] = hb;
        ol[j] = __float2bfloat16(x - __bfloat162float(hb));
    }
}

// ---------------------------------------------------------------------------
// mma.sync QKV projection (bf16 hi/lo split, 3 terms, fp32 accum).
// Unchanged R10 winner.
// ---------------------------------------------------------------------------
#define SM_XHI 0
#define SM_XLO 16384
#define SM_WHI 32768
#define SM_WLO 49152
#define PROJ_SMEM 65536

__global__ __launch_bounds__(256) void proj_mma_kernel() {
    extern __shared__ __align__(1024) char smem[];
    const uint32_t sb = smem_to_u32(smem);
    const int tid = threadIdx.x, w = tid >> 5, lane = tid & 31;
    const int wm = w & 3, wn = w >> 1 >> 1;      // wm 0..3, wn 0..1
    const int mt = blockIdx.x;                   // 0..63
    const int z  = blockIdx.y;                   // 0..2
    const int hg = blockIdx.z;                   // 0..7 (2 heads each)
    const int m0 = mt * 128;
    float* __restrict__ out = (z == 0) ? g_q : (z == 1) ? g_k : g_v;

    float acc[2][8][4];
#pragma unroll
    for (int mi = 0; mi < 2; mi++)
#pragma unroll
        for (int ni = 0; ni < 8; ni++)
#pragma unroll
            for (int r = 0; r < 4; r++) acc[mi][ni][r] = 0.f;

    const int a_row = wm * 32 + (lane & 15);
    const int a_kb  = (lane >> 4) * 16;
    const int b_row = (lane & 7) + ((lane >> 4) << 3);
    const int b_kb  = ((lane >> 3) & 1) * 16;

    for (int c = 0; c < 16; c++) {
        const int k0 = c * 64;
        __syncthreads();
        for (int i = tid; i < 1024; i += 256) {
            const int r = i >> 3, g = i & 7;
            const uint32_t off = SMEM_SWIZZLE_128B((uint32_t)(r * 128 + g * 16));
            const size_t src = (size_t)(m0 + r) * DIN + k0 + g * 8;
            *(uint4*)(smem + SM_XHI + off) = *(const uint4*)(g_xhi + src);
            *(uint4*)(smem + SM_XLO + off) = *(const uint4*)(g_xlo + src);
        }
        for (int i = tid; i < 1024; i += 256) {
            const int hidx = i >> 9;
            const int j = i & 511, r = j >> 3, g = j & 7;
            const size_t src = ((size_t)((z * NH + hg * 2 + hidx) * DE + r)) * DIN + k0 + g * 8;
            const uint32_t off = hidx * 8192 + SMEM_SWIZZLE_128B((uint32_t)(r * 128 + g * 16));
            *(uint4*)(smem + SM_WHI + off) = *(const uint4*)(g_wthi + src);
            *(uint4*)(smem + SM_WLO + off) = *(const uint4*)(g_wtlo + src);
        }
        __syncthreads();

#pragma unroll 1
        for (int ks = 0; ks < 4; ks++) {
            const int kso = ks * 32;
            uint32_t ahi[2][4], alo[2][4];
#pragma unroll
            for (int mi = 0; mi < 2; mi++) {
                const uint32_t off =
                    SMEM_SWIZZLE_128B((uint32_t)((a_row + mi * 16) * 128 + a_kb + kso));
                ldsm_x4(ahi[mi], sb + SM_XHI + off);
                ldsm_x4(alo[mi], sb + SM_XLO + off);
            }
            uint32_t bhi[8][2], blo[8][2];
#pragma unroll
            for (int nb = 0; nb < 4; nb++) {
                const uint32_t off = wn * 8192 +
                    SMEM_SWIZZLE_128B((uint32_t)((nb * 16 + b_row) * 128 + b_kb + kso));
                uint32_t t4[4];
                ldsm_x4(t4, sb + SM_WHI + off);
                bhi[2 * nb][0] = t4[0]; bhi[2 * nb][1] = t4[1];
                bhi[2 * nb + 1][0] = t4[2]; bhi[2 * nb + 1][1] = t4[3];
                ldsm_x4(t4, sb + SM_WLO + off);
                blo[2 * nb][0] = t4[0]; blo[2 * nb][1] = t4[1];
                blo[2 * nb + 1][0] = t4[2]; blo[2 * nb + 1][1] = t4[3];
            }
#pragma unroll
            for (int mi = 0; mi < 2; mi++)
#pragma unroll
                for (int ni = 0; ni < 8; ni++) {
                    mma_bf16(acc[mi][ni], ahi[mi], bhi[ni]);   // xh*wh
                    mma_bf16(acc[mi][ni], ahi[mi], blo[ni]);   // xh*wl
                    mma_bf16(acc[mi][ni], alo[mi], bhi[ni]);   // xl*wh
                }
        }
    }

    const int h = hg * 2 + wn;
#pragma unroll
    for (int mi = 0; mi < 2; mi++) {
#pragma unroll
        for (int ni = 0; ni < 8; ni++) {
            const int e = ni * 8 + (lane & 3) * 2;
#pragma unroll
            for (int half = 0; half < 2; half++) {
                const int m = m0 + wm * 32 + mi * 16 + (lane >> 2) + half * 8;
                const int b = m / SEQ, s = m % SEQ;
                float* __restrict__ o =
                    out + ((size_t)((b * NH + h) * SEQ + s)) * DE + e;
                *(float2*)o = make_float2(acc[mi][ni][half * 2], acc[mi][ni][half * 2 + 1]);
            }
        }
    }
}

// ---------------------------------------------------------------------------
// Causal flash attention — R8/R10 structure, __expf replaced by fast_exp
// (FMA-pipe polynomial) to bypass the quarter-rate MUFU pipe.
// ---------------------------------------------------------------------------
__global__ __launch_bounds__(256, 2) void attn_kernel(float* __restrict__ out)
{
    const int qt = (gridDim.x - 1) - blockIdx.x;
    const int h  = blockIdx.y;
    const int b  = blockIdx.z;
    const int t  = threadIdx.x;

    const int row  = ((t >> 5) << 4) + ((t & 31) >> 1);
    const int half = t & 1;

    const float* __restrict__ Q = g_q + (size_t)((b * NH + h) * SEQ) * DE;
    const float* __restrict__ K = g_k + (size_t)((b * NH + h) * SEQ) * DE;
    const float* __restrict__ V = g_v + (size_t)((b * NH + h) * SEQ) * DE;

    __shared__ __align__(16) float Ks[64][64];
    __shared__ __align__(16) float Vs[64][64];

    const int qrow = qt * 128 + row;

    float q[32];
#pragma unroll
    for (int g4 = 0; g4 < 8; g4++) {
        float4 v = *(const float4*)(Q + (size_t)qrow * DE + (2 * g4 + half) * 4);
        q[g4 * 4 + 0] = v.x * 0.125f;
        q[g4 * 4 + 1] = v.y * 0.125f;
        q[g4 * 4 + 2] = v.z * 0.125f;
        q[g4 * 4 + 3] = v.w * 0.125f;
    }

    float O[32];
#pragma unroll
    for (int e = 0; e < 32; e++) O[e] = 0.f;
    float mrun = -1e30f, lrun = 0.f;

    const int nkt = 2 * qt + 2;
    for (int kt = 0; kt < nkt; kt++) {
        __syncthreads();
#pragma unroll
        for (int it = 0; it < 4; it++) {
            const int fi = it * 256 + t;
            const int r  = fi >> 4;
            const int g  = (fi & 15) << 2;
            *(float4*)(&Ks[r][g]) = *(const float4*)(K + (size_t)(kt * 64 + r) * DE + g);
            *(float4*)(&Vs[r][g]) = *(const float4*)(V + (size_t)(kt * 64 + r) * DE + g);
        }
        __syncthreads();

#pragma unroll
        for (int c = 0; c < 4; c++) {
            const int jbase = kt * 64 + c * 16;
            float s[16];
            float mc = -1e30f;
#pragma unroll
            for (int j = 0; j < 16; j++) {
                const int jj = c * 16 + j;
                float p0 = 0.f, p1 = 0.f;
#pragma unroll
                for (int g4 = 0; g4 < 8; g4 += 2) {
                    float4 ka = *(const float4*)(&Ks[jj][(2 * g4 + half) * 4]);
                    float4 kb = *(const float4*)(&Ks[jj][(2 * (g4 + 1) + half) * 4]);
                    p0 += q[g4*4+0]*ka.x + q[g4*4+1]*ka.y + q[g4*4+2]*ka.z + q[g4*4+3]*ka.w;
                    p1 += q[(g4+1)*4+0]*kb.x + q[(g4+1)*4+1]*kb.y + q[(g4+1)*4+2]*kb.z + q[(g4+1)*4+3]*kb.w;
                }
                float part = p0 + p1;
                part += __shfl_xor_sync(0xffffffffu, part, 1);
                s[j] = (jbase + j > qrow) ? -1e30f : part;
                mc = fmaxf(mc, s[j]);
            }

            const float mnew = fmaxf(mrun, mc);
            if (mnew > mrun) {
                const float corr = fast_exp(mrun - mnew);
                lrun *= corr;
#pragma unroll
                for (int e = 0; e < 32; e++) O[e] *= corr;
                mrun = mnew;
            }

#pragma unroll
            for (int j = 0; j < 16; j++) {
                const int jj = c * 16 + j;
                const float p = fast_exp(s[j] - mrun);
                lrun += p;
#pragma unroll
                for (int g4 = 0; g4 < 8; g4++) {
                    float4 vv = *(const float4*)(&Vs[jj][(2 * g4 + half) * 4]);
                    O[g4 * 4 + 0] += p * vv.x;
                    O[g4 * 4 + 1] += p * vv.y;
                    O[g4 * 4 + 2] += p * vv.z;
                    O[g4 * 4 + 3] += p * vv.w;
                }
            }
        }
    }

    const float inv = 1.f / lrun;
    float* __restrict__ o = out + ((size_t)(b * SEQ + qrow) * (NH * DE)) + h * DE;
#pragma unroll
    for (int g4 = 0; g4 < 8; g4++) {
        float4 v = make_float4(O[g4 * 4 + 0] * inv, O[g4 * 4 + 1] * inv,
                               O[g4 * 4 + 2] * inv, O[g4 * 4 + 3] * inv);
        *(float4*)(o + (2 * g4 + half) * 4) = v;
    }
}

// ---------------------------------------------------------------------------
extern "C" void kernel_launch(void* const* d_in, const int* in_sizes, int n_in,
                              void* d_out, int out_size) {
    (void)in_sizes; (void)n_in; (void)out_size;
    const float* X  = (const float*)d_in[0];
    const float* Wq = (const float*)d_in[1];
    const float* Wk = (const float*)d_in[2];
    const float* Wv = (const float*)d_in[3];
    float* out = (float*)d_out;

    cudaFuncSetAttribute(proj_mma_kernel,
                         cudaFuncAttributeMaxDynamicSharedMemorySize, PROJ_SMEM);

    convert_x_kernel<<<(MROWS * DIN / 4) / 256, 256>>>(X);
    convert_w_kernel<<<3 * NH, 256>>>(Wq, Wk, Wv);

    dim3 gp(64, 3, 8);
    proj_mma_kernel<<<gp, 256, PROJ_SMEM>>>();

    dim3 ga(SEQ / 128, NH, BATCH);
    attn_kernel<<<ga, 256>>>(out);
}

// round 12
// speedup vs baseline: 2.1594x; 2.1594x over previous
#include <cuda_runtime.h>
#include <cuda_bf16.h>
#include <cstdint>

#define BATCH   4
#define SEQ     2048
#define DIN     1024
#define NH      16
#define DE      64
#define MROWS   (BATCH * SEQ)   // 8192

// ---------------------------------------------------------------------------
// Device scratch (static — no allocation). Q/K/V kept as bf16 hi/lo pairs,
// layout [b][h][s][e].
// ---------------------------------------------------------------------------
__device__ __align__(16) __nv_bfloat16 g_qhi[BATCH * NH * SEQ * DE];
__device__ __align__(16) __nv_bfloat16 g_qlo[BATCH * NH * SEQ * DE];
__device__ __align__(16) __nv_bfloat16 g_khi[BATCH * NH * SEQ * DE];
__device__ __align__(16) __nv_bfloat16 g_klo[BATCH * NH * SEQ * DE];
__device__ __align__(16) __nv_bfloat16 g_vhi[BATCH * NH * SEQ * DE];
__device__ __align__(16) __nv_bfloat16 g_vlo[BATCH * NH * SEQ * DE];

__device__ __align__(16) __nv_bfloat16 g_xhi[MROWS * DIN];
__device__ __align__(16) __nv_bfloat16 g_xlo[MROWS * DIN];
// W transposed+split: [z][h][e][k], k contiguous (1024)
__device__ __align__(16) __nv_bfloat16 g_wthi[3 * NH * DE * DIN];
__device__ __align__(16) __nv_bfloat16 g_wtlo[3 * NH * DE * DIN];

// ---------------------------------------------------------------------------
// Warp-level MMA helpers (baseline PTX — works on sm_100 non-'a' target).
// ---------------------------------------------------------------------------
__device__ __forceinline__ uint32_t smem_to_u32(const void* p) {
    uint32_t a;
    asm("{ .reg .u64 t; cvta.to.shared.u64 t, %1; cvt.u32.u64 %0, t; }" : "=r"(a) : "l"(p));
    return a;
}
__device__ __forceinline__ void ldsm_x4(uint32_t* r, uint32_t addr) {
    asm volatile("ldmatrix.sync.aligned.m8n8.x4.shared.b16 {%0,%1,%2,%3}, [%4];"
                 : "=r"(r[0]), "=r"(r[1]), "=r"(r[2]), "=r"(r[3]) : "r"(addr));
}
__device__ __forceinline__ void ldsm_x4_trans(uint32_t* r, uint32_t addr) {
    asm volatile("ldmatrix.sync.aligned.m8n8.x4.trans.shared.b16 {%0,%1,%2,%3}, [%4];"
                 : "=r"(r[0]), "=r"(r[1]), "=r"(r[2]), "=r"(r[3]) : "r"(addr));
}
__device__ __forceinline__ void mma_bf16(float* c, const uint32_t* a, const uint32_t* b) {
    asm volatile("mma.sync.aligned.m16n8k16.row.col.f32.bf16.bf16.f32 "
                 "{%0,%1,%2,%3}, {%4,%5,%6,%7}, {%8,%9}, {%0,%1,%2,%3};"
                 : "+f"(c[0]), "+f"(c[1]), "+f"(c[2]), "+f"(c[3])
                 : "r"(a[0]), "r"(a[1]), "r"(a[2]), "r"(a[3]), "r"(b[0]), "r"(b[1]));
}
// pack {lo=f0, hi=f1} into one u32 of bf16x2
__device__ __forceinline__ uint32_t pack_bf16x2(float f0, float f1) {
    uint32_t r;
    asm("cvt.rn.bf16x2.f32 %0, %1, %2;" : "=r"(r) : "f"(f1), "f"(f0));
    return r;
}
#define SMEM_SWIZZLE_128B(o) ((o) ^ (((o) >> 3) & 0x70))

// ---------------------------------------------------------------------------
// Convert X -> bf16 hi/lo (same [m][k] layout).
// ---------------------------------------------------------------------------
__global__ __launch_bounds__(256) void convert_x_kernel(const float* __restrict__ X) {
    const int i = blockIdx.x * 256 + threadIdx.x;   // float4 index
    float4 v = ((const float4*)X)[i];
    float xs[4] = {v.x, v.y, v.z, v.w};
    union { __nv_bfloat16 h[4]; uint2 u; } hi, lo;
#pragma unroll
    for (int j = 0; j < 4; j++) {
        __nv_bfloat16 h = __float2bfloat16(xs[j]);
        hi.h[j] = h;
        lo.h[j] = __float2bfloat16(xs[j] - __bfloat162float(h));
    }
    ((uint2*)g_xhi)[i] = hi.u;
    ((uint2*)g_xlo)[i] = lo.u;
}

// ---------------------------------------------------------------------------
// Convert + transpose W: [z][h][k][e] fp32 -> [z][h][e][k] bf16 hi/lo.
// ---------------------------------------------------------------------------
__global__ __launch_bounds__(256) void convert_w_kernel(
    const float* __restrict__ Wq, const float* __restrict__ Wk, const float* __restrict__ Wv) {
    const int zh = blockIdx.x;
    const int z = zh / NH, h = zh % NH;
    const float* __restrict__ W = (z == 0) ? Wq : (z == 1) ? Wk : Wv;
    const float* __restrict__ Wh = W + (size_t)h * DIN * DE;
    __nv_bfloat16* __restrict__ oh = g_wthi + (size_t)zh * DE * DIN;
    __nv_bfloat16* __restrict__ ol = g_wtlo + (size_t)zh * DE * DIN;
    for (int j = threadIdx.x; j < DE * DIN; j += 256) {
        const int e = j / DIN, k = j % DIN;
        const float x = Wh[(size_t)k * DE + e];
        const __nv_bfloat16 hb = __float2bfloat16(x);
        oh[j] = hb;
        ol[j] = __float2bfloat16(x - __bfloat162float(hb));
    }
}

// ---------------------------------------------------------------------------
// mma.sync QKV projection (bf16 hi/lo split, 3 terms, fp32 accum).
// R10 mainloop; epilogue now writes bf16 hi/lo Q/K/V (Q pre-scaled by 0.125).
// ---------------------------------------------------------------------------
#define SM_XHI 0
#define SM_XLO 16384
#define SM_WHI 32768
#define SM_WLO 49152
#define PROJ_SMEM 65536

__global__ __launch_bounds__(256) void proj_mma_kernel() {
    extern __shared__ __align__(1024) char smem[];
    const uint32_t sb = smem_to_u32(smem);
    const int tid = threadIdx.x, w = tid >> 5, lane = tid & 31;
    const int wm = w & 3, wn = w >> 1 >> 1;      // wm 0..3, wn 0..1
    const int mt = blockIdx.x;                   // 0..63
    const int z  = blockIdx.y;                   // 0..2
    const int hg = blockIdx.z;                   // 0..7 (2 heads each)
    const int m0 = mt * 128;
    __nv_bfloat16* __restrict__ ohi = (z == 0) ? g_qhi : (z == 1) ? g_khi : g_vhi;
    __nv_bfloat16* __restrict__ olo = (z == 0) ? g_qlo : (z == 1) ? g_klo : g_vlo;
    const float scale = (z == 0) ? 0.125f : 1.0f;   // fold 1/sqrt(64) into Q

    float acc[2][8][4];
#pragma unroll
    for (int mi = 0; mi < 2; mi++)
#pragma unroll
        for (int ni = 0; ni < 8; ni++)
#pragma unroll
            for (int r = 0; r < 4; r++) acc[mi][ni][r] = 0.f;

    const int a_row = wm * 32 + (lane & 15);
    const int a_kb  = (lane >> 4) * 16;
    const int b_row = (lane & 7) + ((lane >> 4) << 3);
    const int b_kb  = ((lane >> 3) & 1) * 16;

    for (int c = 0; c < 16; c++) {
        const int k0 = c * 64;
        __syncthreads();
        for (int i = tid; i < 1024; i += 256) {
            const int r = i >> 3, g = i & 7;
            const uint32_t off = SMEM_SWIZZLE_128B((uint32_t)(r * 128 + g * 16));
            const size_t src = (size_t)(m0 + r) * DIN + k0 + g * 8;
            *(uint4*)(smem + SM_XHI + off) = *(const uint4*)(g_xhi + src);
            *(uint4*)(smem + SM_XLO + off) = *(const uint4*)(g_xlo + src);
        }
        for (int i = tid; i < 1024; i += 256) {
            const int hidx = i >> 9;
            const int j = i & 511, r = j >> 3, g = j & 7;
            const size_t src = ((size_t)((z * NH + hg * 2 + hidx) * DE + r)) * DIN + k0 + g * 8;
            const uint32_t off = hidx * 8192 + SMEM_SWIZZLE_128B((uint32_t)(r * 128 + g * 16));
            *(uint4*)(smem + SM_WHI + off) = *(const uint4*)(g_wthi + src);
            *(uint4*)(smem + SM_WLO + off) = *(const uint4*)(g_wtlo + src);
        }
        __syncthreads();

#pragma unroll 1
        for (int ks = 0; ks < 4; ks++) {
            const int kso = ks * 32;
            uint32_t ahi[2][4], alo[2][4];
#pragma unroll
            for (int mi = 0; mi < 2; mi++) {
                const uint32_t off =
                    SMEM_SWIZZLE_128B((uint32_t)((a_row + mi * 16) * 128 + a_kb + kso));
                ldsm_x4(ahi[mi], sb + SM_XHI + off);
                ldsm_x4(alo[mi], sb + SM_XLO + off);
            }
            uint32_t bhi[8][2], blo[8][2];
#pragma unroll
            for (int nb = 0; nb < 4; nb++) {
                const uint32_t off = wn * 8192 +
                    SMEM_SWIZZLE_128B((uint32_t)((nb * 16 + b_row) * 128 + b_kb + kso));
                uint32_t t4[4];
                ldsm_x4(t4, sb + SM_WHI + off);
                bhi[2 * nb][0] = t4[0]; bhi[2 * nb][1] = t4[1];
                bhi[2 * nb + 1][0] = t4[2]; bhi[2 * nb + 1][1] = t4[3];
                ldsm_x4(t4, sb + SM_WLO + off);
                blo[2 * nb][0] = t4[0]; blo[2 * nb][1] = t4[1];
                blo[2 * nb + 1][0] = t4[2]; blo[2 * nb + 1][1] = t4[3];
            }
#pragma unroll
            for (int mi = 0; mi < 2; mi++)
#pragma unroll
                for (int ni = 0; ni < 8; ni++) {
                    mma_bf16(acc[mi][ni], ahi[mi], bhi[ni]);   // xh*wh
                    mma_bf16(acc[mi][ni], ahi[mi], blo[ni]);   // xh*wl
                    mma_bf16(acc[mi][ni], alo[mi], bhi[ni]);   // xl*wh
                }
        }
    }

    const int h = hg * 2 + wn;
#pragma unroll
    for (int mi = 0; mi < 2; mi++) {
#pragma unroll
        for (int ni = 0; ni < 8; ni++) {
            const int e = ni * 8 + (lane & 3) * 2;
#pragma unroll
            for (int half = 0; half < 2; half++) {
                const int m = m0 + wm * 32 + mi * 16 + (lane >> 2) + half * 8;
                const int b = m / SEQ, s = m % SEQ;
                const float v0 = acc[mi][ni][half * 2] * scale;
                const float v1 = acc[mi][ni][half * 2 + 1] * scale;
                const uint32_t hp = pack_bf16x2(v0, v1);
                const float h0 = __uint_as_float(hp << 16);
                const float h1 = __uint_as_float(hp & 0xffff0000u);
                const uint32_t lp = pack_bf16x2(v0 - h0, v1 - h1);
                const size_t off = ((size_t)((b * NH + h) * SEQ + s)) * DE + e;
                *(uint32_t*)(ohi + off) = hp;
                *(uint32_t*)(olo + off) = lp;
            }
        }
    }
}

// ---------------------------------------------------------------------------
// mma.sync causal flash attention.
// CTA = 128 q-rows of one (b,h); 8 warps, warp = 16 q-rows. 64-key tiles.
// S = QK^T: 3-term bf16 hi/lo; B-frags via ldmatrix on K[key][e].
// Softmax on S fragments (quad shfl reductions, __expf).
// O += P V: 3-term (Ph Vh + Ph Vl + Pl Vh); A-frags from S regs (direct
// mapping), B-frags via ldmatrix.trans on V[key][e]. fp32 O rescaled in-place.
// ---------------------------------------------------------------------------
__global__ __launch_bounds__(256) void attn_mma_kernel(float* __restrict__ out)
{
    __shared__ __align__(1024) __nv_bfloat16 sKh[64 * 64];
    __shared__ __align__(1024) __nv_bfloat16 sKl[64 * 64];
    __shared__ __align__(1024) __nv_bfloat16 sVh[64 * 64];
    __shared__ __align__(1024) __nv_bfloat16 sVl[64 * 64];

    const int qt = (gridDim.x - 1) - blockIdx.x;
    const int h  = blockIdx.y;
    const int b  = blockIdx.z;
    const int tid = threadIdx.x, w = tid >> 5, lane = tid & 31;
    const int ar = lane >> 2, ac = (lane & 3) * 2;

    const size_t bh = (size_t)(b * NH + h) * SEQ * DE;
    const __nv_bfloat16* __restrict__ Qhi = g_qhi + bh;
    const __nv_bfloat16* __restrict__ Qlo = g_qlo + bh;
    const __nv_bfloat16* __restrict__ Khi = g_khi + bh;
    const __nv_bfloat16* __restrict__ Klo = g_klo + bh;
    const __nv_bfloat16* __restrict__ Vhi = g_vhi + bh;
    const __nv_bfloat16* __restrict__ Vlo = g_vlo + bh;

    const uint32_t skh = smem_to_u32(sKh), skl = smem_to_u32(sKl);
    const uint32_t svh = smem_to_u32(sVh), svl = smem_to_u32(sVl);

    const int q0 = qt * 128 + w * 16;        // warp's first q-row

    // Q fragments (hi/lo), 4 k-steps of 16 over e=64.
    uint32_t qh[4][4], ql[4][4];
#pragma unroll
    for (int ks = 0; ks < 4; ks++) {
        const int r0 = q0 + ar, r1 = r0 + 8;
        const int c0 = ks * 16 + ac, c1 = c0 + 8;
        qh[ks][0] = *(const uint32_t*)(Qhi + (size_t)r0 * DE + c0);
        qh[ks][1] = *(const uint32_t*)(Qhi + (size_t)r1 * DE + c0);
        qh[ks][2] = *(const uint32_t*)(Qhi + (size_t)r0 * DE + c1);
        qh[ks][3] = *(const uint32_t*)(Qhi + (size_t)r1 * DE + c1);
        ql[ks][0] = *(const uint32_t*)(Qlo + (size_t)r0 * DE + c0);
        ql[ks][1] = *(const uint32_t*)(Qlo + (size_t)r1 * DE + c0);
        ql[ks][2] = *(const uint32_t*)(Qlo + (size_t)r0 * DE + c1);
        ql[ks][3] = *(const uint32_t*)(Qlo + (size_t)r1 * DE + c1);
    }

    float O[8][4];
#pragma unroll
    for (int et = 0; et < 8; et++)
#pragma unroll
        for (int r = 0; r < 4; r++) O[et][r] = 0.f;
    float m0r = -1e30f, m1r = -1e30f, l0r = 0.f, l1r = 0.f;

    // ldmatrix lane-address components
    const int lj = lane >> 3, l7 = lane & 7;

    const int nkt = 2 * qt + 2;
    for (int kt = 0; kt < nkt; kt++) {
        __syncthreads();   // previous tile's ldmatrix reads done
        // Stage K/V hi/lo tiles (64x64 bf16 each, SW128 128B rows).
#pragma unroll
        for (int u = 0; u < 8; u++) {
            const int j = ((u & 1) << 8) + tid;      // 0..511
            const int r = j >> 3, g = j & 7;
            const uint32_t off = SMEM_SWIZZLE_128B((uint32_t)(r * 128 + g * 16));
            const size_t src = (size_t)(kt * 64 + r) * DE + g * 8;
            if ((u >> 1) == 0)      *(uint4*)((char*)sKh + off) = *(const uint4*)(Khi + src);
            else if ((u >> 1) == 1) *(uint4*)((char*)sKl + off) = *(const uint4*)(Klo + src);
            else if ((u >> 1) == 2) *(uint4*)((char*)sVh + off) = *(const uint4*)(Vhi + src);
            else                    *(uint4*)((char*)sVl + off) = *(const uint4*)(Vlo + src);
        }
        __syncthreads();

        if (kt * 64 > q0 + 15) continue;   // tile entirely in the causal future

        // ---- S = Q K^T over this 64-key tile ----
        float S[8][4];
#pragma unroll
        for (int nt = 0; nt < 8; nt++)
#pragma unroll
            for (int r = 0; r < 4; r++) S[nt][r] = 0.f;

#pragma unroll 1
        for (int ks = 0; ks < 4; ks++) {
#pragma unroll
            for (int ntp = 0; ntp < 4; ntp++) {
                // x4: m0=(keys ntp*16+0-7, e-half0) m1=(.., half1) m2/m3=keys+8
                const int krow = ntp * 16 + ((lj >> 1) << 3) + l7;
                const uint32_t off =
                    SMEM_SWIZZLE_128B((uint32_t)(krow * 128 + (lj & 1) * 16 + ks * 32));
                uint32_t th[4], tl[4];
                ldsm_x4(th, skh + off);
                ldsm_x4(tl, skl + off);
                mma_bf16(S[2 * ntp],     qh[ks], th + 0);
                mma_bf16(S[2 * ntp],     qh[ks], tl + 0);
                mma_bf16(S[2 * ntp],     ql[ks], th + 0);
                mma_bf16(S[2 * ntp + 1], qh[ks], th + 2);
                mma_bf16(S[2 * ntp + 1], qh[ks], tl + 2);
                mma_bf16(S[2 * ntp + 1], ql[ks], th + 2);
            }
        }

        // ---- causal mask (diagonal band only) ----
        const int r0g = q0 + ar, r1g = r0g + 8;
        if (kt * 64 + 63 > q0) {
#pragma unroll
            for (int nt = 0; nt < 8; nt++) {
                const int cb = kt * 64 + nt * 8 + ac;
                if (cb     > r0g) S[nt][0] = -1e30f;
                if (cb + 1 > r0g) S[nt][1] = -1e30f;
                if (cb     > r1g) S[nt][2] = -1e30f;
                if (cb + 1 > r1g) S[nt][3] = -1e30f;
            }
        }

        // ---- online softmax ----
        float mc0 = -1e30f, mc1 = -1e30f;
#pragma unroll
        for (int nt = 0; nt < 8; nt++) {
            mc0 = fmaxf(mc0, fmaxf(S[nt][0], S[nt][1]));
            mc1 = fmaxf(mc1, fmaxf(S[nt][2], S[nt][3]));
        }
        mc0 = fmaxf(mc0, __shfl_xor_sync(0xffffffffu, mc0, 1));
        mc0 = fmaxf(mc0, __shfl_xor_sync(0xffffffffu, mc0, 2));
        mc1 = fmaxf(mc1, __shfl_xor_sync(0xffffffffu, mc1, 1));
        mc1 = fmaxf(mc1, __shfl_xor_sync(0xffffffffu, mc1, 2));

        const float mn0 = fmaxf(m0r, mc0), mn1 = fmaxf(m1r, mc1);
        const float cr0 = __expf(m0r - mn0), cr1 = __expf(m1r - mn1);
        m0r = mn0; m1r = mn1;
        l0r *= cr0; l1r *= cr1;
#pragma unroll
        for (int et = 0; et < 8; et++) {
            O[et][0] *= cr0; O[et][1] *= cr0;
            O[et][2] *= cr1; O[et][3] *= cr1;
        }

        float rs0 = 0.f, rs1 = 0.f;
#pragma unroll
        for (int nt = 0; nt < 8; nt++) {
            S[nt][0] = __expf(S[nt][0] - mn0);
            S[nt][1] = __expf(S[nt][1] - mn0);
            S[nt][2] = __expf(S[nt][2] - mn1);
            S[nt][3] = __expf(S[nt][3] - mn1);
            rs0 += S[nt][0] + S[nt][1];
            rs1 += S[nt][2] + S[nt][3];
        }
        rs0 += __shfl_xor_sync(0xffffffffu, rs0, 1);
        rs0 += __shfl_xor_sync(0xffffffffu, rs0, 2);
        rs1 += __shfl_xor_sync(0xffffffffu, rs1, 1);
        rs1 += __shfl_xor_sync(0xffffffffu, rs1, 2);
        l0r += rs0; l1r += rs1;

        // ---- O += P V ----
#pragma unroll 1
        for (int kks = 0; kks < 4; kks++) {
            // A-frags from S (P) in registers, hi + lo
            uint32_t ah[4], al[4];
#pragma unroll
            for (int q2 = 0; q2 < 2; q2++) {       // ntiles 2kks + q2
                const int nt = 2 * kks + q2;
                const uint32_t h0 = pack_bf16x2(S[nt][0], S[nt][1]);
                const uint32_t h1 = pack_bf16x2(S[nt][2], S[nt][3]);
                ah[2 * q2]     = h0;
                ah[2 * q2 + 1] = h1;
                const float f00 = __uint_as_float(h0 << 16);
                const float f01 = __uint_as_float(h0 & 0xffff0000u);
                const float f10 = __uint_as_float(h1 << 16);
                const float f11 = __uint_as_float(h1 & 0xffff0000u);
                al[2 * q2]     = pack_bf16x2(S[nt][0] - f00, S[nt][1] - f01);
                al[2 * q2 + 1] = pack_bf16x2(S[nt][2] - f10, S[nt][3] - f11);
            }
            // hmm: a-frag order must be {a0=(r,k0-7), a1=(r+8,k0-7), a2=(r,k8-15), a3=(r+8,k8-15)}
            // rearrange: current ah = {nt0 rows0, nt0 rows8, nt1 rows0, nt1 rows8}
            // needed:              {nt0 rows0, nt0 rows8, nt1 rows0, nt1 rows8}  — identical. OK.
#pragma unroll
            for (int etp = 0; etp < 4; etp++) {
                // x4.trans: m0=(keys kks*16+0-7, e etp*16+0-7) m1=(keys+8, same e)
                //           m2/m3 = e+8
                const int krow = kks * 16 + ((lj & 1) << 3) + l7;
                const uint32_t off =
                    SMEM_SWIZZLE_128B((uint32_t)(krow * 128 + etp * 32 + (lj >> 1) * 16));
                uint32_t tvh[4], tvl[4];
                ldsm_x4_trans(tvh, svh + off);
                ldsm_x4_trans(tvl, svl + off);
                mma_bf16(O[2 * etp],     ah, tvh + 0);
                mma_bf16(O[2 * etp],     ah, tvl + 0);
                mma_bf16(O[2 * etp],     al, tvh + 0);
                mma_bf16(O[2 * etp + 1], ah, tvh + 2);
                mma_bf16(O[2 * etp + 1], ah, tvl + 2);
                mma_bf16(O[2 * etp + 1], al, tvh + 2);
            }
        }
    }

    // ---- finalize + store ----
    const float i0 = 1.f / l0r, i1 = 1.f / l1r;
    const int row0 = qt * 128 + w * 16 + ar;
    const size_t ob0 = (size_t)(b * SEQ + row0) * (NH * DE) + h * DE;
    const size_t ob1 = (size_t)(b * SEQ + row0 + 8) * (NH * DE) + h * DE;
#pragma unroll
    for (int et = 0; et < 8; et++) {
        const int e = et * 8 + ac;
        *(float2*)(out + ob0 + e) = make_float2(O[et][0] * i0, O[et][1] * i0);
        *(float2*)(out + ob1 + e) = make_float2(O[et][2] * i1, O[et][3] * i1);
    }
}

// ---------------------------------------------------------------------------
extern "C" void kernel_launch(void* const* d_in, const int* in_sizes, int n_in,
                              void* d_out, int out_size) {
    (void)in_sizes; (void)n_in; (void)out_size;
    const float* X  = (const float*)d_in[0];
    const float* Wq = (const float*)d_in[1];
    const float* Wk = (const float*)d_in[2];
    const float* Wv = (const float*)d_in[3];
    float* out = (float*)d_out;

    cudaFuncSetAttribute(proj_mma_kernel,
                         cudaFuncAttributeMaxDynamicSharedMemorySize, PROJ_SMEM);

    convert_x_kernel<<<(MROWS * DIN / 4) / 256, 256>>>(X);
    convert_w_kernel<<<3 * NH, 256>>>(Wq, Wk, Wv);

    dim3 gp(64, 3, 8);
    proj_mma_kernel<<<gp, 256, PROJ_SMEM>>>();

    dim3 ga(SEQ / 128, NH, BATCH);
    attn_mma_kernel<<<ga, 256>>>(out);
}

// round 15
// speedup vs baseline: 2.2557x; 1.0446x over previous
#include <cuda_runtime.h>
#include <cuda_bf16.h>
#include <cstdint>

#define BATCH   4
#define SEQ     2048
#define DIN     1024
#define NH      16
#define DE      64
#define MROWS   (BATCH * SEQ)   // 8192

// ---------------------------------------------------------------------------
// Device scratch (static — no allocation). Q/K/V kept as bf16 hi/lo pairs,
// layout [b][h][s][e].
// ---------------------------------------------------------------------------
__device__ __align__(16) __nv_bfloat16 g_qhi[BATCH * NH * SEQ * DE];
__device__ __align__(16) __nv_bfloat16 g_qlo[BATCH * NH * SEQ * DE];
__device__ __align__(16) __nv_bfloat16 g_khi[BATCH * NH * SEQ * DE];
__device__ __align__(16) __nv_bfloat16 g_klo[BATCH * NH * SEQ * DE];
__device__ __align__(16) __nv_bfloat16 g_vhi[BATCH * NH * SEQ * DE];
__device__ __align__(16) __nv_bfloat16 g_vlo[BATCH * NH * SEQ * DE];

__device__ __align__(16) __nv_bfloat16 g_xhi[MROWS * DIN];
__device__ __align__(16) __nv_bfloat16 g_xlo[MROWS * DIN];
// W transposed+split: [z][h][e][k], k contiguous (1024)
__device__ __align__(16) __nv_bfloat16 g_wthi[3 * NH * DE * DIN];
__device__ __align__(16) __nv_bfloat16 g_wtlo[3 * NH * DE * DIN];

// ---------------------------------------------------------------------------
// Warp-level MMA helpers (baseline PTX — works on sm_100 non-'a' target).
// ---------------------------------------------------------------------------
__device__ __forceinline__ uint32_t smem_to_u32(const void* p) {
    uint32_t a;
    asm("{ .reg .u64 t; cvta.to.shared.u64 t, %1; cvt.u32.u64 %0, t; }" : "=r"(a) : "l"(p));
    return a;
}
__device__ __forceinline__ void ldsm_x4(uint32_t* r, uint32_t addr) {
    asm volatile("ldmatrix.sync.aligned.m8n8.x4.shared.b16 {%0,%1,%2,%3}, [%4];"
                 : "=r"(r[0]), "=r"(r[1]), "=r"(r[2]), "=r"(r[3]) : "r"(addr));
}
__device__ __forceinline__ void ldsm_x4_trans(uint32_t* r, uint32_t addr) {
    asm volatile("ldmatrix.sync.aligned.m8n8.x4.trans.shared.b16 {%0,%1,%2,%3}, [%4];"
                 : "=r"(r[0]), "=r"(r[1]), "=r"(r[2]), "=r"(r[3]) : "r"(addr));
}
__device__ __forceinline__ void mma_bf16(float* c, const uint32_t* a, const uint32_t* b) {
    asm volatile("mma.sync.aligned.m16n8k16.row.col.f32.bf16.bf16.f32 "
                 "{%0,%1,%2,%3}, {%4,%5,%6,%7}, {%8,%9}, {%0,%1,%2,%3};"
                 : "+f"(c[0]), "+f"(c[1]), "+f"(c[2]), "+f"(c[3])
                 : "r"(a[0]), "r"(a[1]), "r"(a[2]), "r"(a[3]), "r"(b[0]), "r"(b[1]));
}
// pack {lo=f0, hi=f1} into one u32 of bf16x2
__device__ __forceinline__ uint32_t pack_bf16x2(float f0, float f1) {
    uint32_t r;
    asm("cvt.rn.bf16x2.f32 %0, %1, %2;" : "=r"(r) : "f"(f1), "f"(f0));
    return r;
}
__device__ __forceinline__ void cp_async16(uint32_t dst, const void* src) {
    asm volatile("cp.async.cg.shared.global [%0], [%1], 16;" :: "r"(dst), "l"(src));
}
#define CP_ASYNC_COMMIT() asm volatile("cp.async.commit_group;" ::: "memory")
#define CP_ASYNC_WAIT_1() asm volatile("cp.async.wait_group 1;" ::: "memory")
#define CP_ASYNC_WAIT_0() asm volatile("cp.async.wait_group 0;" ::: "memory")
#define SMEM_SWIZZLE_128B(o) ((o) ^ (((o) >> 3) & 0x70))

// ---------------------------------------------------------------------------
// Convert X -> bf16 hi/lo (same [m][k] layout).
// ---------------------------------------------------------------------------
__global__ __launch_bounds__(256) void convert_x_kernel(const float* __restrict__ X) {
    const int i = blockIdx.x * 256 + threadIdx.x;   // float4 index
    float4 v = ((const float4*)X)[i];
    float xs[4] = {v.x, v.y, v.z, v.w};
    union { __nv_bfloat16 h[4]; uint2 u; } hi, lo;
#pragma unroll
    for (int j = 0; j < 4; j++) {
        __nv_bfloat16 h = __float2bfloat16(xs[j]);
        hi.h[j] = h;
        lo.h[j] = __float2bfloat16(xs[j] - __bfloat162float(h));
    }
    ((uint2*)g_xhi)[i] = hi.u;
    ((uint2*)g_xlo)[i] = lo.u;
}

// ---------------------------------------------------------------------------
// Convert + transpose W: [z][h][k][e] fp32 -> [z][h][e][k] bf16 hi/lo.
// ---------------------------------------------------------------------------
__global__ __launch_bounds__(256) void convert_w_kernel(
    const float* __restrict__ Wq, const float* __restrict__ Wk, const float* __restrict__ Wv) {
    const int zh = blockIdx.x;
    const int z = zh / NH, h = zh % NH;
    const float* __restrict__ W = (z == 0) ? Wq : (z == 1) ? Wk : Wv;
    const float* __restrict__ Wh = W + (size_t)h * DIN * DE;
    __nv_bfloat16* __restrict__ oh = g_wthi + (size_t)zh * DE * DIN;
    __nv_bfloat16* __restrict__ ol = g_wtlo + (size_t)zh * DE * DIN;
    for (int j = threadIdx.x; j < DE * DIN; j += 256) {
        const int e = j / DIN, k = j % DIN;
        const float x = Wh[(size_t)k * DE + e];
        const __nv_bfloat16 hb = __float2bfloat16(x);
        oh[j] = hb;
        ol[j] = __float2bfloat16(x - __bfloat162float(hb));
    }
}

// ---------------------------------------------------------------------------
// mma.sync QKV projection (bf16 hi/lo split, 3 terms, fp32 accum).
// Unchanged R12 winner (epilogue writes bf16 hi/lo Q/K/V, Q pre-scaled).
// ---------------------------------------------------------------------------
#define SM_XHI 0
#define SM_XLO 16384
#define SM_WHI 32768
#define SM_WLO 49152
#define PROJ_SMEM 65536

__global__ __launch_bounds__(256) void proj_mma_kernel() {
    extern __shared__ __align__(1024) char smem[];
    const uint32_t sb = smem_to_u32(smem);
    const int tid = threadIdx.x, w = tid >> 5, lane = tid & 31;
    const int wm = w & 3, wn = w >> 1 >> 1;      // wm 0..3, wn 0..1
    const int mt = blockIdx.x;                   // 0..63
    const int z  = blockIdx.y;                   // 0..2
    const int hg = blockIdx.z;                   // 0..7 (2 heads each)
    const int m0 = mt * 128;
    __nv_bfloat16* __restrict__ ohi = (z == 0) ? g_qhi : (z == 1) ? g_khi : g_vhi;
    __nv_bfloat16* __restrict__ olo = (z == 0) ? g_qlo : (z == 1) ? g_klo : g_vlo;
    const float scale = (z == 0) ? 0.125f : 1.0f;   // fold 1/sqrt(64) into Q

    float acc[2][8][4];
#pragma unroll
    for (int mi = 0; mi < 2; mi++)
#pragma unroll
        for (int ni = 0; ni < 8; ni++)
#pragma unroll
            for (int r = 0; r < 4; r++) acc[mi][ni][r] = 0.f;

    const int a_row = wm * 32 + (lane & 15);
    const int a_kb  = (lane >> 4) * 16;
    const int b_row = (lane & 7) + ((lane >> 4) << 3);
    const int b_kb  = ((lane >> 3) & 1) * 16;

    for (int c = 0; c < 16; c++) {
        const int k0 = c * 64;
        __syncthreads();
        for (int i = tid; i < 1024; i += 256) {
            const int r = i >> 3, g = i & 7;
            const uint32_t off = SMEM_SWIZZLE_128B((uint32_t)(r * 128 + g * 16));
            const size_t src = (size_t)(m0 + r) * DIN + k0 + g * 8;
            *(uint4*)(smem + SM_XHI + off) = *(const uint4*)(g_xhi + src);
            *(uint4*)(smem + SM_XLO + off) = *(const uint4*)(g_xlo + src);
        }
        for (int i = tid; i < 1024; i += 256) {
            const int hidx = i >> 9;
            const int j = i & 511, r = j >> 3, g = j & 7;
            const size_t src = ((size_t)((z * NH + hg * 2 + hidx) * DE + r)) * DIN + k0 + g * 8;
            const uint32_t off = hidx * 8192 + SMEM_SWIZZLE_128B((uint32_t)(r * 128 + g * 16));
            *(uint4*)(smem + SM_WHI + off) = *(const uint4*)(g_wthi + src);
            *(uint4*)(smem + SM_WLO + off) = *(const uint4*)(g_wtlo + src);
        }
        __syncthreads();

#pragma unroll 1
        for (int ks = 0; ks < 4; ks++) {
            const int kso = ks * 32;
            uint32_t ahi[2][4], alo[2][4];
#pragma unroll
            for (int mi = 0; mi < 2; mi++) {
                const uint32_t off =
                    SMEM_SWIZZLE_128B((uint32_t)((a_row + mi * 16) * 128 + a_kb + kso));
                ldsm_x4(ahi[mi], sb + SM_XHI + off);
                ldsm_x4(alo[mi], sb + SM_XLO + off);
            }
            uint32_t bhi[8][2], blo[8][2];
#pragma unroll
            for (int nb = 0; nb < 4; nb++) {
                const uint32_t off = wn * 8192 +
                    SMEM_SWIZZLE_128B((uint32_t)((nb * 16 + b_row) * 128 + b_kb + kso));
                uint32_t t4[4];
                ldsm_x4(t4, sb + SM_WHI + off);
                bhi[2 * nb][0] = t4[0]; bhi[2 * nb][1] = t4[1];
                bhi[2 * nb + 1][0] = t4[2]; bhi[2 * nb + 1][1] = t4[3];
                ldsm_x4(t4, sb + SM_WLO + off);
                blo[2 * nb][0] = t4[0]; blo[2 * nb][1] = t4[1];
                blo[2 * nb + 1][0] = t4[2]; blo[2 * nb + 1][1] = t4[3];
            }
#pragma unroll
            for (int mi = 0; mi < 2; mi++)
#pragma unroll
                for (int ni = 0; ni < 8; ni++) {
                    mma_bf16(acc[mi][ni], ahi[mi], bhi[ni]);   // xh*wh
                    mma_bf16(acc[mi][ni], ahi[mi], blo[ni]);   // xh*wl
                    mma_bf16(acc[mi][ni], alo[mi], bhi[ni]);   // xl*wh
                }
        }
    }

    const int h = hg * 2 + wn;
#pragma unroll
    for (int mi = 0; mi < 2; mi++) {
#pragma unroll
        for (int ni = 0; ni < 8; ni++) {
            const int e = ni * 8 + (lane & 3) * 2;
#pragma unroll
            for (int half = 0; half < 2; half++) {
                const int m = m0 + wm * 32 + mi * 16 + (lane >> 2) + half * 8;
                const int b = m / SEQ, s = m % SEQ;
                const float v0 = acc[mi][ni][half * 2] * scale;
                const float v1 = acc[mi][ni][half * 2 + 1] * scale;
                const uint32_t hp = pack_bf16x2(v0, v1);
                const float h0 = __uint_as_float(hp << 16);
                const float h1 = __uint_as_float(hp & 0xffff0000u);
                const uint32_t lp = pack_bf16x2(v0 - h0, v1 - h1);
                const size_t off = ((size_t)((b * NH + h) * SEQ + s)) * DE + e;
                *(uint32_t*)(ohi + off) = hp;
                *(uint32_t*)(olo + off) = lp;
            }
        }
    }
}

// ---------------------------------------------------------------------------
// mma.sync causal flash attention, cp.async double-buffered K/V pipeline.
// CTA = 128 q-rows of one (b,h); 8 warps, warp = 16 q-rows. 64-key tiles.
// S = QK^T: 3-term bf16 hi/lo. O += PV: 3-term (Ph*Vh + Ph*Vl + Pl*Vh) —
// R14 showed the Pl*Vh term is required (dropping it -> rel_err 1.15e-3).
// Dynamic smem 64KB: 2 stages x (Kh|Kl|Vh|Vl) 8KB each.
// ---------------------------------------------------------------------------
#define ATTN_SMEM 65536

__global__ __launch_bounds__(256) void attn_mma_kernel(float* __restrict__ out)
{
    extern __shared__ __align__(1024) char asmem[];
    const uint32_t sb = smem_to_u32(asmem);

    const int qt = (gridDim.x - 1) - blockIdx.x;
    const int h  = blockIdx.y;
    const int b  = blockIdx.z;
    const int tid = threadIdx.x, w = tid >> 5, lane = tid & 31;
    const int ar = lane >> 2, ac = (lane & 3) * 2;

    const size_t bh = (size_t)(b * NH + h) * SEQ * DE;
    const __nv_bfloat16* __restrict__ Qhi = g_qhi + bh;
    const __nv_bfloat16* __restrict__ Qlo = g_qlo + bh;
    const __nv_bfloat16* srcs[4] = {g_khi + bh, g_klo + bh, g_vhi + bh, g_vlo + bh};

    const int q0 = qt * 128 + w * 16;        // warp's first q-row

    // Q fragments (hi/lo), 4 k-steps of 16 over e=64.
    uint32_t qh[4][4], ql[4][4];
#pragma unroll
    for (int ks = 0; ks < 4; ks++) {
        const int r0 = q0 + ar, r1 = r0 + 8;
        const int c0 = ks * 16 + ac, c1 = c0 + 8;
        qh[ks][0] = *(const uint32_t*)(Qhi + (size_t)r0 * DE + c0);
        qh[ks][1] = *(const uint32_t*)(Qhi + (size_t)r1 * DE + c0);
        qh[ks][2] = *(const uint32_t*)(Qhi + (size_t)r0 * DE + c1);
        qh[ks][3] = *(const uint32_t*)(Qhi + (size_t)r1 * DE + c1);
        ql[ks][0] = *(const uint32_t*)(Qlo + (size_t)r0 * DE + c0);
        ql[ks][1] = *(const uint32_t*)(Qlo + (size_t)r1 * DE + c0);
        ql[ks][2] = *(const uint32_t*)(Qlo + (size_t)r0 * DE + c1);
        ql[ks][3] = *(const uint32_t*)(Qlo + (size_t)r1 * DE + c1);
    }

    float O[8][4];
#pragma unroll
    for (int et = 0; et < 8; et++)
#pragma unroll
        for (int r = 0; r < 4; r++) O[et][r] = 0.f;
    float m0r = -1e30f, m1r = -1e30f, l0r = 0.f, l1r = 0.f;

    const int lj = lane >> 3, l7 = lane & 7;
    const int nkt = 2 * qt + 2;

    // --- cp.async tile stager: 4 regions x 8KB into stage buffer ---
    auto stage_tile = [&](int kt, int stg) {
        const uint32_t base = sb + stg * 32768;
#pragma unroll
        for (int u = 0; u < 8; u++) {
            const int j = ((u & 1) << 8) + tid;      // 0..511
            const int r = j >> 3, g = j & 7;
            const uint32_t off = SMEM_SWIZZLE_128B((uint32_t)(r * 128 + g * 16));
            const size_t src = (size_t)(kt * 64 + r) * DE + g * 8;
            cp_async16(base + (u >> 1) * 8192 + off, srcs[u >> 1] + src);
        }
        CP_ASYNC_COMMIT();
    };

    stage_tile(0, 0);

    for (int kt = 0; kt < nkt; kt++) {
        if (kt + 1 < nkt) {
            stage_tile(kt + 1, (kt + 1) & 1);
            CP_ASYNC_WAIT_1();
        } else {
            CP_ASYNC_WAIT_0();
        }
        __syncthreads();   // tile kt visible to all; prior compute drained

        if (kt * 64 <= q0 + 15) {
            const uint32_t cb = sb + (kt & 1) * 32768;
            const uint32_t skh = cb, skl = cb + 8192, svh = cb + 16384, svl = cb + 24576;

            // ---- S = Q K^T over this 64-key tile ----
            float S[8][4];
#pragma unroll
            for (int nt = 0; nt < 8; nt++)
#pragma unroll
                for (int r = 0; r < 4; r++) S[nt][r] = 0.f;

#pragma unroll 1
            for (int ks = 0; ks < 4; ks++) {
#pragma unroll
                for (int ntp = 0; ntp < 4; ntp++) {
                    const int krow = ntp * 16 + ((lj >> 1) << 3) + l7;
                    const uint32_t off =
                        SMEM_SWIZZLE_128B((uint32_t)(krow * 128 + (lj & 1) * 16 + ks * 32));
                    uint32_t th[4], tl[4];
                    ldsm_x4(th, skh + off);
                    ldsm_x4(tl, skl + off);
                    mma_bf16(S[2 * ntp],     qh[ks], th + 0);
                    mma_bf16(S[2 * ntp],     qh[ks], tl + 0);
                    mma_bf16(S[2 * ntp],     ql[ks], th + 0);
                    mma_bf16(S[2 * ntp + 1], qh[ks], th + 2);
                    mma_bf16(S[2 * ntp + 1], qh[ks], tl + 2);
                    mma_bf16(S[2 * ntp + 1], ql[ks], th + 2);
                }
            }

            // ---- causal mask (diagonal band only) ----
            const int r0g = q0 + ar, r1g = r0g + 8;
            if (kt * 64 + 63 > q0) {
#pragma unroll
                for (int nt = 0; nt < 8; nt++) {
                    const int cbn = kt * 64 + nt * 8 + ac;
                    if (cbn     > r0g) S[nt][0] = -1e30f;
                    if (cbn + 1 > r0g) S[nt][1] = -1e30f;
                    if (cbn     > r1g) S[nt][2] = -1e30f;
                    if (cbn + 1 > r1g) S[nt][3] = -1e30f;
                }
            }

            // ---- online softmax ----
            float mc0 = -1e30f, mc1 = -1e30f;
#pragma unroll
            for (int nt = 0; nt < 8; nt++) {
                mc0 = fmaxf(mc0, fmaxf(S[nt][0], S[nt][1]));
                mc1 = fmaxf(mc1, fmaxf(S[nt][2], S[nt][3]));
            }
            mc0 = fmaxf(mc0, __shfl_xor_sync(0xffffffffu, mc0, 1));
            mc0 = fmaxf(mc0, __shfl_xor_sync(0xffffffffu, mc0, 2));
            mc1 = fmaxf(mc1, __shfl_xor_sync(0xffffffffu, mc1, 1));
            mc1 = fmaxf(mc1, __shfl_xor_sync(0xffffffffu, mc1, 2));

            const float mn0 = fmaxf(m0r, mc0), mn1 = fmaxf(m1r, mc1);
            const float cr0 = __expf(m0r - mn0), cr1 = __expf(m1r - mn1);
            m0r = mn0; m1r = mn1;
            l0r *= cr0; l1r *= cr1;
#pragma unroll
            for (int et = 0; et < 8; et++) {
                O[et][0] *= cr0; O[et][1] *= cr0;
                O[et][2] *= cr1; O[et][3] *= cr1;
            }

            float rs0 = 0.f, rs1 = 0.f;
#pragma unroll
            for (int nt = 0; nt < 8; nt++) {
                S[nt][0] = __expf(S[nt][0] - mn0);
                S[nt][1] = __expf(S[nt][1] - mn0);
                S[nt][2] = __expf(S[nt][2] - mn1);
                S[nt][3] = __expf(S[nt][3] - mn1);
                rs0 += S[nt][0] + S[nt][1];
                rs1 += S[nt][2] + S[nt][3];
            }
            rs0 += __shfl_xor_sync(0xffffffffu, rs0, 1);
            rs0 += __shfl_xor_sync(0xffffffffu, rs0, 2);
            rs1 += __shfl_xor_sync(0xffffffffu, rs1, 1);
            rs1 += __shfl_xor_sync(0xffffffffu, rs1, 2);
            l0r += rs0; l1r += rs1;

            // ---- O += P V (3-term: Ph*Vh + Ph*Vl + Pl*Vh) ----
#pragma unroll 1
            for (int kks = 0; kks < 4; kks++) {
                uint32_t ah[4], al[4];
#pragma unroll
                for (int q2 = 0; q2 < 2; q2++) {
                    const int nt = 2 * kks + q2;
                    const uint32_t h0 = pack_bf16x2(S[nt][0], S[nt][1]);
                    const uint32_t h1 = pack_bf16x2(S[nt][2], S[nt][3]);
                    ah[2 * q2]     = h0;
                    ah[2 * q2 + 1] = h1;
                    const float f00 = __uint_as_float(h0 << 16);
                    const float f01 = __uint_as_float(h0 & 0xffff0000u);
                    const float f10 = __uint_as_float(h1 << 16);
                    const float f11 = __uint_as_float(h1 & 0xffff0000u);
                    al[2 * q2]     = pack_bf16x2(S[nt][0] - f00, S[nt][1] - f01);
                    al[2 * q2 + 1] = pack_bf16x2(S[nt][2] - f10, S[nt][3] - f11);
                }
#pragma unroll
                for (int etp = 0; etp < 4; etp++) {
                    const int krow = kks * 16 + ((lj & 1) << 3) + l7;
                    const uint32_t off =
                        SMEM_SWIZZLE_128B((uint32_t)(krow * 128 + etp * 32 + (lj >> 1) * 16));
                    uint32_t tvh[4], tvl[4];
                    ldsm_x4_trans(tvh, svh + off);
                    ldsm_x4_trans(tvl, svl + off);
                    mma_bf16(O[2 * etp],     ah, tvh + 0);
                    mma_bf16(O[2 * etp],     ah, tvl + 0);
                    mma_bf16(O[2 * etp],     al, tvh + 0);
                    mma_bf16(O[2 * etp + 1], ah, tvh + 2);
                    mma_bf16(O[2 * etp + 1], ah, tvl + 2);
                    mma_bf16(O[2 * etp + 1], al, tvh + 2);
                }
            }
        }

        __syncthreads();   // all reads of buffer kt&1 done before it's restaged
    }

    // ---- finalize + store ----
    const float i0 = 1.f / l0r, i1 = 1.f / l1r;
    const int row0 = qt * 128 + w * 16 + ar;
    const size_t ob0 = (size_t)(b * SEQ + row0) * (NH * DE) + h * DE;
    const size_t ob1 = (size_t)(b * SEQ + row0 + 8) * (NH * DE) + h * DE;
#pragma unroll
    for (int et = 0; et < 8; et++) {
        const int e = et * 8 + ac;
        *(float2*)(out + ob0 + e) = make_float2(O[et][0] * i0, O[et][1] * i0);
        *(float2*)(out + ob1 + e) = make_float2(O[et][2] * i1, O[et][3] * i1);
    }
}

// ---------------------------------------------------------------------------
extern "C" void kernel_launch(void* const* d_in, const int* in_sizes, int n_in,
                              void* d_out, int out_size) {
    (void)in_sizes; (void)n_in; (void)out_size;
    const float* X  = (const float*)d_in[0];
    const float* Wq = (const float*)d_in[1];
    const float* Wk = (const float*)d_in[2];
    const float* Wv = (const float*)d_in[3];
    float* out = (float*)d_out;

    cudaFuncSetAttribute(proj_mma_kernel,
                         cudaFuncAttributeMaxDynamicSharedMemorySize, PROJ_SMEM);
    cudaFuncSetAttribute(attn_mma_kernel,
                         cudaFuncAttributeMaxDynamicSharedMemorySize, ATTN_SMEM);

    convert_x_kernel<<<(MROWS * DIN / 4) / 256, 256>>>(X);
    convert_w_kernel<<<3 * NH, 256>>>(Wq, Wk, Wv);

    dim3 gp(64, 3, 8);
    proj_mma_kernel<<<gp, 256, PROJ_SMEM>>>();

    dim3 ga(SEQ / 128, NH, BATCH);
    attn_mma_kernel<<<ga, 256, ATTN_SMEM>>>(out);
}

// round 16
// speedup vs baseline: 2.3786x; 1.0545x over previous
#include <cuda_runtime.h>
#include <cuda_bf16.h>
#include <cuda_fp16.h>
#include <cstdint>

#define BATCH   4
#define SEQ     2048
#define DIN     1024
#define NH      16
#define DE      64
#define MROWS   (BATCH * SEQ)   // 8192

// ---------------------------------------------------------------------------
// Device scratch (static — no allocation).
// Q: fp16 hi/lo (pre-scaled by 0.125*log2e). K: fp16 single. V: fp16 hi/lo.
// Layout [b][h][s][e].
// ---------------------------------------------------------------------------
__device__ __align__(16) __half g_qhi[BATCH * NH * SEQ * DE];
__device__ __align__(16) __half g_qlo[BATCH * NH * SEQ * DE];
__device__ __align__(16) __half g_khi[BATCH * NH * SEQ * DE];
__device__ __align__(16) __half g_vhi[BATCH * NH * SEQ * DE];
__device__ __align__(16) __half g_vlo[BATCH * NH * SEQ * DE];

__device__ __align__(16) __nv_bfloat16 g_xhi[MROWS * DIN];
__device__ __align__(16) __nv_bfloat16 g_xlo[MROWS * DIN];
// W transposed+split: [z][h][e][k], k contiguous (1024)
__device__ __align__(16) __nv_bfloat16 g_wthi[3 * NH * DE * DIN];
__device__ __align__(16) __nv_bfloat16 g_wtlo[3 * NH * DE * DIN];

// ---------------------------------------------------------------------------
// Warp-level MMA helpers (baseline PTX — works on sm_100 non-'a' target).
// ---------------------------------------------------------------------------
__device__ __forceinline__ uint32_t smem_to_u32(const void* p) {
    uint32_t a;
    asm("{ .reg .u64 t; cvta.to.shared.u64 t, %1; cvt.u32.u64 %0, t; }" : "=r"(a) : "l"(p));
    return a;
}
__device__ __forceinline__ void ldsm_x4(uint32_t* r, uint32_t addr) {
    asm volatile("ldmatrix.sync.aligned.m8n8.x4.shared.b16 {%0,%1,%2,%3}, [%4];"
                 : "=r"(r[0]), "=r"(r[1]), "=r"(r[2]), "=r"(r[3]) : "r"(addr));
}
__device__ __forceinline__ void ldsm_x4_trans(uint32_t* r, uint32_t addr) {
    asm volatile("ldmatrix.sync.aligned.m8n8.x4.trans.shared.b16 {%0,%1,%2,%3}, [%4];"
                 : "=r"(r[0]), "=r"(r[1]), "=r"(r[2]), "=r"(r[3]) : "r"(addr));
}
__device__ __forceinline__ void mma_bf16(float* c, const uint32_t* a, const uint32_t* b) {
    asm volatile("mma.sync.aligned.m16n8k16.row.col.f32.bf16.bf16.f32 "
                 "{%0,%1,%2,%3}, {%4,%5,%6,%7}, {%8,%9}, {%0,%1,%2,%3};"
                 : "+f"(c[0]), "+f"(c[1]), "+f"(c[2]), "+f"(c[3])
                 : "r"(a[0]), "r"(a[1]), "r"(a[2]), "r"(a[3]), "r"(b[0]), "r"(b[1]));
}
__device__ __forceinline__ void mma_f16(float* c, const uint32_t* a, const uint32_t* b) {
    asm volatile("mma.sync.aligned.m16n8k16.row.col.f32.f16.f16.f32 "
                 "{%0,%1,%2,%3}, {%4,%5,%6,%7}, {%8,%9}, {%0,%1,%2,%3};"
                 : "+f"(c[0]), "+f"(c[1]), "+f"(c[2]), "+f"(c[3])
                 : "r"(a[0]), "r"(a[1]), "r"(a[2]), "r"(a[3]), "r"(b[0]), "r"(b[1]));
}
// pack {lo=f0, hi=f1}
__device__ __forceinline__ uint32_t pack_bf16x2(float f0, float f1) {
    uint32_t r;
    asm("cvt.rn.bf16x2.f32 %0, %1, %2;" : "=r"(r) : "f"(f1), "f"(f0));
    return r;
}
__device__ __forceinline__ uint32_t pack_f16x2(float f0, float f1) {
    uint32_t r;
    asm("cvt.rn.f16x2.f32 %0, %1, %2;" : "=r"(r) : "f"(f1), "f"(f0));
    return r;
}
__device__ __forceinline__ void cp_async16(uint32_t dst, const void* src) {
    asm volatile("cp.async.cg.shared.global [%0], [%1], 16;" :: "r"(dst), "l"(src));
}
#define CP_ASYNC_COMMIT() asm volatile("cp.async.commit_group;" ::: "memory")
#define CP_ASYNC_WAIT_1() asm volatile("cp.async.wait_group 1;" ::: "memory")
#define CP_ASYNC_WAIT_0() asm volatile("cp.async.wait_group 0;" ::: "memory")
#define SMEM_SWIZZLE_128B(o) ((o) ^ (((o) >> 3) & 0x70))

// ---------------------------------------------------------------------------
// Convert X -> bf16 hi/lo (same [m][k] layout).
// ---------------------------------------------------------------------------
__global__ __launch_bounds__(256) void convert_x_kernel(const float* __restrict__ X) {
    const int i = blockIdx.x * 256 + threadIdx.x;   // float4 index
    float4 v = ((const float4*)X)[i];
    float xs[4] = {v.x, v.y, v.z, v.w};
    union { __nv_bfloat16 h[4]; uint2 u; } hi, lo;
#pragma unroll
    for (int j = 0; j < 4; j++) {
        __nv_bfloat16 h = __float2bfloat16(xs[j]);
        hi.h[j] = h;
        lo.h[j] = __float2bfloat16(xs[j] - __bfloat162float(h));
    }
    ((uint2*)g_xhi)[i] = hi.u;
    ((uint2*)g_xlo)[i] = lo.u;
}

// ---------------------------------------------------------------------------
// Convert + transpose W: [z][h][k][e] fp32 -> [z][h][e][k] bf16 hi/lo.
// ---------------------------------------------------------------------------
__global__ __launch_bounds__(256) void convert_w_kernel(
    const float* __restrict__ Wq, const float* __restrict__ Wk, const float* __restrict__ Wv) {
    const int zh = blockIdx.x;
    const int z = zh / NH, h = zh % NH;
    const float* __restrict__ W = (z == 0) ? Wq : (z == 1) ? Wk : Wv;
    const float* __restrict__ Wh = W + (size_t)h * DIN * DE;
    __nv_bfloat16* __restrict__ oh = g_wthi + (size_t)zh * DE * DIN;
    __nv_bfloat16* __restrict__ ol = g_wtlo + (size_t)zh * DE * DIN;
    for (int j = threadIdx.x; j < DE * DIN; j += 256) {
        const int e = j / DIN, k = j % DIN;
        const float x = Wh[(size_t)k * DE + e];
        const __nv_bfloat16 hb = __float2bfloat16(x);
        oh[j] = hb;
        ol[j] = __float2bfloat16(x - __bfloat162float(hb));
    }
}

// ---------------------------------------------------------------------------
// mma.sync QKV projection (bf16 hi/lo split, 3 terms, fp32 accum).
// Mainloop = R12/R15 winner. Epilogue emits fp16:
//   z=0 (Q): fp16 hi/lo, scaled by 0.125*log2(e)  (exp2-domain scores)
//   z=1 (K): fp16 single
//   z=2 (V): fp16 hi/lo
// ---------------------------------------------------------------------------
#define SM_XHI 0
#define SM_XLO 16384
#define SM_WHI 32768
#define SM_WLO 49152
#define PROJ_SMEM 65536
#define QSCALE 0.1803368801112533f   // 0.125 * log2(e)

__global__ __launch_bounds__(256) void proj_mma_kernel() {
    extern __shared__ __align__(1024) char smem[];
    const uint32_t sb = smem_to_u32(smem);
    const int tid = threadIdx.x, w = tid >> 5, lane = tid & 31;
    const int wm = w & 3, wn = w >> 1 >> 1;      // wm 0..3, wn 0..1
    const int mt = blockIdx.x;                   // 0..63
    const int z  = blockIdx.y;                   // 0..2
    const int hg = blockIdx.z;                   // 0..7 (2 heads each)
    const int m0 = mt * 128;
    __half* __restrict__ ohi = (z == 0) ? g_qhi : (z == 1) ? g_khi : g_vhi;
    __half* __restrict__ olo = (z == 0) ? g_qlo : (z == 1) ? g_qlo : g_vlo;  // z=1 unused
    const float scale = (z == 0) ? QSCALE : 1.0f;

    float acc[2][8][4];
#pragma unroll
    for (int mi = 0; mi < 2; mi++)
#pragma unroll
        for (int ni = 0; ni < 8; ni++)
#pragma unroll
            for (int r = 0; r < 4; r++) acc[mi][ni][r] = 0.f;

    const int a_row = wm * 32 + (lane & 15);
    const int a_kb  = (lane >> 4) * 16;
    const int b_row = (lane & 7) + ((lane >> 4) << 3);
    const int b_kb  = ((lane >> 3) & 1) * 16;

    for (int c = 0; c < 16; c++) {
        const int k0 = c * 64;
        __syncthreads();
        for (int i = tid; i < 1024; i += 256) {
            const int r = i >> 3, g = i & 7;
            const uint32_t off = SMEM_SWIZZLE_128B((uint32_t)(r * 128 + g * 16));
            const size_t src = (size_t)(m0 + r) * DIN + k0 + g * 8;
            *(uint4*)(smem + SM_XHI + off) = *(const uint4*)(g_xhi + src);
            *(uint4*)(smem + SM_XLO + off) = *(const uint4*)(g_xlo + src);
        }
        for (int i = tid; i < 1024; i += 256) {
            const int hidx = i >> 9;
            const int j = i & 511, r = j >> 3, g = j & 7;
            const size_t src = ((size_t)((z * NH + hg * 2 + hidx) * DE + r)) * DIN + k0 + g * 8;
            const uint32_t off = hidx * 8192 + SMEM_SWIZZLE_128B((uint32_t)(r * 128 + g * 16));
            *(uint4*)(smem + SM_WHI + off) = *(const uint4*)(g_wthi + src);
            *(uint4*)(smem + SM_WLO + off) = *(const uint4*)(g_wtlo + src);
        }
        __syncthreads();

#pragma unroll 1
        for (int ks = 0; ks < 4; ks++) {
            const int kso = ks * 32;
            uint32_t ahi[2][4], alo[2][4];
#pragma unroll
            for (int mi = 0; mi < 2; mi++) {
                const uint32_t off =
                    SMEM_SWIZZLE_128B((uint32_t)((a_row + mi * 16) * 128 + a_kb + kso));
                ldsm_x4(ahi[mi], sb + SM_XHI + off);
                ldsm_x4(alo[mi], sb + SM_XLO + off);
            }
            uint32_t bhi[8][2], blo[8][2];
#pragma unroll
            for (int nb = 0; nb < 4; nb++) {
                const uint32_t off = wn * 8192 +
                    SMEM_SWIZZLE_128B((uint32_t)((nb * 16 + b_row) * 128 + b_kb + kso));
                uint32_t t4[4];
                ldsm_x4(t4, sb + SM_WHI + off);
                bhi[2 * nb][0] = t4[0]; bhi[2 * nb][1] = t4[1];
                bhi[2 * nb + 1][0] = t4[2]; bhi[2 * nb + 1][1] = t4[3];
                ldsm_x4(t4, sb + SM_WLO + off);
                blo[2 * nb][0] = t4[0]; blo[2 * nb][1] = t4[1];
                blo[2 * nb + 1][0] = t4[2]; blo[2 * nb + 1][1] = t4[3];
            }
#pragma unroll
            for (int mi = 0; mi < 2; mi++)
#pragma unroll
                for (int ni = 0; ni < 8; ni++) {
                    mma_bf16(acc[mi][ni], ahi[mi], bhi[ni]);   // xh*wh
                    mma_bf16(acc[mi][ni], ahi[mi], blo[ni]);   // xh*wl
                    mma_bf16(acc[mi][ni], alo[mi], bhi[ni]);   // xl*wh
                }
        }
    }

    const int h = hg * 2 + wn;
#pragma unroll
    for (int mi = 0; mi < 2; mi++) {
#pragma unroll
        for (int ni = 0; ni < 8; ni++) {
            const int e = ni * 8 + (lane & 3) * 2;
#pragma unroll
            for (int half = 0; half < 2; half++) {
                const int m = m0 + wm * 32 + mi * 16 + (lane >> 2) + half * 8;
                const int b = m / SEQ, s = m % SEQ;
                const float v0 = acc[mi][ni][half * 2] * scale;
                const float v1 = acc[mi][ni][half * 2 + 1] * scale;
                const uint32_t hp = pack_f16x2(v0, v1);
                const size_t off = ((size_t)((b * NH + h) * SEQ + s)) * DE + e;
                *(uint32_t*)(ohi + off) = hp;
                if (z != 1) {   // Q and V also store fp16 residuals
                    const __half2 hh = *reinterpret_cast<const __half2*>(&hp);
                    const float f00 = __low2float(hh), f01 = __high2float(hh);
                    *(uint32_t*)(olo + off) = pack_f16x2(v0 - f00, v1 - f01);
                }
            }
        }
    }
}

// ---------------------------------------------------------------------------
// mma.sync causal flash attention (fp16 2-term), cp.async double-buffered.
// CTA = 128 q-rows of one (b,h); 8 warps, warp = 16 q-rows. 64-key tiles.
// S = (Qh+Ql) K   : 2 fp16 MMAs per fragment (Q exact fp16 hi/lo, K fp16).
// O += P (Vh+Vl)  : 2 fp16 MMAs (P single fp16, V exact fp16 hi/lo).
// Scores in exp2 domain (log2e folded into Q) -> exp2f (single MUFU).
// O-rescale skipped (warp-uniform) when no row max advances.
// Dynamic smem 48KB: 2 stages x (K|Vh|Vl) 8KB each.
// ---------------------------------------------------------------------------
#define ATTN_SMEM 49152

__global__ __launch_bounds__(256) void attn_mma_kernel(float* __restrict__ out)
{
    extern __shared__ __align__(1024) char asmem[];
    const uint32_t sb = smem_to_u32(asmem);

    const int qt = (gridDim.x - 1) - blockIdx.x;
    const int h  = blockIdx.y;
    const int b  = blockIdx.z;
    const int tid = threadIdx.x, w = tid >> 5, lane = tid & 31;
    const int ar = lane >> 2, ac = (lane & 3) * 2;

    const size_t bh = (size_t)(b * NH + h) * SEQ * DE;
    const __half* __restrict__ Qhi = g_qhi + bh;
    const __half* __restrict__ Qlo = g_qlo + bh;
    const __half* srcs[3] = {g_khi + bh, g_vhi + bh, g_vlo + bh};

    const int q0 = qt * 128 + w * 16;        // warp's first q-row

    // Q fragments (hi/lo), 4 k-steps of 16 over e=64.
    uint32_t qh[4][4], ql[4][4];
#pragma unroll
    for (int ks = 0; ks < 4; ks++) {
        const int r0 = q0 + ar, r1 = r0 + 8;
        const int c0 = ks * 16 + ac, c1 = c0 + 8;
        qh[ks][0] = *(const uint32_t*)(Qhi + (size_t)r0 * DE + c0);
        qh[ks][1] = *(const uint32_t*)(Qhi + (size_t)r1 * DE + c0);
        qh[ks][2] = *(const uint32_t*)(Qhi + (size_t)r0 * DE + c1);
        qh[ks][3] = *(const uint32_t*)(Qhi + (size_t)r1 * DE + c1);
        ql[ks][0] = *(const uint32_t*)(Qlo + (size_t)r0 * DE + c0);
        ql[ks][1] = *(const uint32_t*)(Qlo + (size_t)r1 * DE + c0);
        ql[ks][2] = *(const uint32_t*)(Qlo + (size_t)r0 * DE + c1);
        ql[ks][3] = *(const uint32_t*)(Qlo + (size_t)r1 * DE + c1);
    }

    float O[8][4];
#pragma unroll
    for (int et = 0; et < 8; et++)
#pragma unroll
        for (int r = 0; r < 4; r++) O[et][r] = 0.f;
    float m0r = -1e30f, m1r = -1e30f, l0r = 0.f, l1r = 0.f;

    const int lj = lane >> 3, l7 = lane & 7;
    const int nkt = 2 * qt + 2;

    // --- cp.async tile stager: 3 regions x 8KB into stage buffer ---
    auto stage_tile = [&](int kt, int stg) {
        const uint32_t base = sb + stg * 24576;
#pragma unroll
        for (int u = 0; u < 6; u++) {
            const int j = ((u & 1) << 8) + tid;      // 0..511
            const int r = j >> 3, g = j & 7;
            const uint32_t off = SMEM_SWIZZLE_128B((uint32_t)(r * 128 + g * 16));
            const size_t src = (size_t)(kt * 64 + r) * DE + g * 8;
            cp_async16(base + (u >> 1) * 8192 + off, srcs[u >> 1] + src);
        }
        CP_ASYNC_COMMIT();
    };

    stage_tile(0, 0);

    for (int kt = 0; kt < nkt; kt++) {
        if (kt + 1 < nkt) {
            stage_tile(kt + 1, (kt + 1) & 1);
            CP_ASYNC_WAIT_1();
        } else {
            CP_ASYNC_WAIT_0();
        }
        __syncthreads();   // tile kt visible to all; prior compute drained

        if (kt * 64 <= q0 + 15) {
            const uint32_t cb = sb + (kt & 1) * 24576;
            const uint32_t sk = cb, svh = cb + 8192, svl = cb + 16384;

            // ---- S = Q K^T over this 64-key tile (2-term fp16) ----
            float S[8][4];
#pragma unroll
            for (int nt = 0; nt < 8; nt++)
#pragma unroll
                for (int r = 0; r < 4; r++) S[nt][r] = 0.f;

#pragma unroll 1
            for (int ks = 0; ks < 4; ks++) {
#pragma unroll
                for (int ntp = 0; ntp < 4; ntp++) {
                    const int krow = ntp * 16 + ((lj >> 1) << 3) + l7;
                    const uint32_t off =
                        SMEM_SWIZZLE_128B((uint32_t)(krow * 128 + (lj & 1) * 16 + ks * 32));
                    uint32_t th[4];
                    ldsm_x4(th, sk + off);
                    mma_f16(S[2 * ntp],     qh[ks], th + 0);
                    mma_f16(S[2 * ntp],     ql[ks], th + 0);
                    mma_f16(S[2 * ntp + 1], qh[ks], th + 2);
                    mma_f16(S[2 * ntp + 1], ql[ks], th + 2);
                }
            }

            // ---- causal mask (diagonal band only) ----
            const int r0g = q0 + ar, r1g = r0g + 8;
            if (kt * 64 + 63 > q0) {
#pragma unroll
                for (int nt = 0; nt < 8; nt++) {
                    const int cbn = kt * 64 + nt * 8 + ac;
                    if (cbn     > r0g) S[nt][0] = -1e30f;
                    if (cbn + 1 > r0g) S[nt][1] = -1e30f;
                    if (cbn     > r1g) S[nt][2] = -1e30f;
                    if (cbn + 1 > r1g) S[nt][3] = -1e30f;
                }
            }

            // ---- online softmax (exp2 domain) ----
            float mc0 = -1e30f, mc1 = -1e30f;
#pragma unroll
            for (int nt = 0; nt < 8; nt++) {
                mc0 = fmaxf(mc0, fmaxf(S[nt][0], S[nt][1]));
                mc1 = fmaxf(mc1, fmaxf(S[nt][2], S[nt][3]));
            }
            mc0 = fmaxf(mc0, __shfl_xor_sync(0xffffffffu, mc0, 1));
            mc0 = fmaxf(mc0, __shfl_xor_sync(0xffffffffu, mc0, 2));
            mc1 = fmaxf(mc1, __shfl_xor_sync(0xffffffffu, mc1, 1));
            mc1 = fmaxf(mc1, __shfl_xor_sync(0xffffffffu, mc1, 2));

            const float mn0 = fmaxf(m0r, mc0), mn1 = fmaxf(m1r, mc1);
            if (__any_sync(0xffffffffu, (mn0 > m0r) || (mn1 > m1r))) {
                const float cr0 = exp2f(m0r - mn0), cr1 = exp2f(m1r - mn1);
                m0r = mn0; m1r = mn1;
                l0r *= cr0; l1r *= cr1;
#pragma unroll
                for (int et = 0; et < 8; et++) {
                    O[et][0] *= cr0; O[et][1] *= cr0;
                    O[et][2] *= cr1; O[et][3] *= cr1;
                }
            }

            float rs0 = 0.f, rs1 = 0.f;
#pragma unroll
            for (int nt = 0; nt < 8; nt++) {
                S[nt][0] = exp2f(S[nt][0] - m0r);
                S[nt][1] = exp2f(S[nt][1] - m0r);
                S[nt][2] = exp2f(S[nt][2] - m1r);
                S[nt][3] = exp2f(S[nt][3] - m1r);
                rs0 += S[nt][0] + S[nt][1];
                rs1 += S[nt][2] + S[nt][3];
            }
            rs0 += __shfl_xor_sync(0xffffffffu, rs0, 1);
            rs0 += __shfl_xor_sync(0xffffffffu, rs0, 2);
            rs1 += __shfl_xor_sync(0xffffffffu, rs1, 1);
            rs1 += __shfl_xor_sync(0xffffffffu, rs1, 2);
            l0r += rs0; l1r += rs1;

            // ---- O += P V (2-term fp16: P*Vh + P*Vl) ----
#pragma unroll 1
            for (int kks = 0; kks < 4; kks++) {
                uint32_t ah[4];
#pragma unroll
                for (int q2 = 0; q2 < 2; q2++) {
                    const int nt = 2 * kks + q2;
                    ah[2 * q2]     = pack_f16x2(S[nt][0], S[nt][1]);
                    ah[2 * q2 + 1] = pack_f16x2(S[nt][2], S[nt][3]);
                }
#pragma unroll
                for (int etp = 0; etp < 4; etp++) {
                    const int krow = kks * 16 + ((lj & 1) << 3) + l7;
                    const uint32_t off =
                        SMEM_SWIZZLE_128B((uint32_t)(krow * 128 + etp * 32 + (lj >> 1) * 16));
                    uint32_t tvh[4], tvl[4];
                    ldsm_x4_trans(tvh, svh + off);
                    ldsm_x4_trans(tvl, svl + off);
                    mma_f16(O[2 * etp],     ah, tvh + 0);
                    mma_f16(O[2 * etp],     ah, tvl + 0);
                    mma_f16(O[2 * etp + 1], ah, tvh + 2);
                    mma_f16(O[2 * etp + 1], ah, tvl + 2);
                }
            }
        }

        __syncthreads();   // all reads of buffer kt&1 done before it's restaged
    }

    // ---- finalize + store ----
    const float i0 = 1.f / l0r, i1 = 1.f / l1r;
    const int row0 = qt * 128 + w * 16 + ar;
    const size_t ob0 = (size_t)(b * SEQ + row0) * (NH * DE) + h * DE;
    const size_t ob1 = (size_t)(b * SEQ + row0 + 8) * (NH * DE) + h * DE;
#pragma unroll
    for (int et = 0; et < 8; et++) {
        const int e = et * 8 + ac;
        *(float2*)(out + ob0 + e) = make_float2(O[et][0] * i0, O[et][1] * i0);
        *(float2*)(out + ob1 + e) = make_float2(O[et][2] * i1, O[et][3] * i1);
    }
}

// ---------------------------------------------------------------------------
extern "C" void kernel_launch(void* const* d_in, const int* in_sizes, int n_in,
                              void* d_out, int out_size) {
    (void)in_sizes; (void)n_in; (void)out_size;
    const float* X  = (const float*)d_in[0];
    const float* Wq = (const float*)d_in[1];
    const float* Wk = (const float*)d_in[2];
    const float* Wv = (const float*)d_in[3];
    float* out = (float*)d_out;

    cudaFuncSetAttribute(proj_mma_kernel,
                         cudaFuncAttributeMaxDynamicSharedMemorySize, PROJ_SMEM);
    cudaFuncSetAttribute(attn_mma_kernel,
                         cudaFuncAttributeMaxDynamicSharedMemorySize, ATTN_SMEM);

    convert_x_kernel<<<(MROWS * DIN / 4) / 256, 256>>>(X);
    convert_w_kernel<<<3 * NH, 256>>>(Wq, Wk, Wv);

    dim3 gp(64, 3, 8);
    proj_mma_kernel<<<gp, 256, PROJ_SMEM>>>();

    dim3 ga(SEQ / 128, NH, BATCH);
    attn_mma_kernel<<<ga, 256, ATTN_SMEM>>>(out);
}

// round 17
// speedup vs baseline: 3.2988x; 1.3869x over previous
#include <cuda_runtime.h>
#include <cuda_bf16.h>
#include <cuda_fp16.h>
#include <cstdint>

#define BATCH   4
#define SEQ     2048
#define DIN     1024
#define NH      16
#define DE      64
#define MROWS   (BATCH * SEQ)   // 8192

// ---------------------------------------------------------------------------
// Device scratch (static — no allocation).
// Q: fp16 hi/lo (pre-scaled by 0.125*log2e). K: fp16 single. V: fp16 hi/lo.
// X: fp16 hi/lo. W transposed: single fp16, [z][h][e][k].
// ---------------------------------------------------------------------------
__device__ __align__(16) __half g_qhi[BATCH * NH * SEQ * DE];
__device__ __align__(16) __half g_qlo[BATCH * NH * SEQ * DE];
__device__ __align__(16) __half g_khi[BATCH * NH * SEQ * DE];
__device__ __align__(16) __half g_vhi[BATCH * NH * SEQ * DE];
__device__ __align__(16) __half g_vlo[BATCH * NH * SEQ * DE];

__device__ __align__(16) __half g_xhi[MROWS * DIN];
__device__ __align__(16) __half g_xlo[MROWS * DIN];
__device__ __align__(16) __half g_wt[3 * NH * DE * DIN];

// ---------------------------------------------------------------------------
// Warp-level MMA helpers (baseline PTX — works on sm_100 non-'a' target).
// ---------------------------------------------------------------------------
__device__ __forceinline__ uint32_t smem_to_u32(const void* p) {
    uint32_t a;
    asm("{ .reg .u64 t; cvta.to.shared.u64 t, %1; cvt.u32.u64 %0, t; }" : "=r"(a) : "l"(p));
    return a;
}
__device__ __forceinline__ void ldsm_x4(uint32_t* r, uint32_t addr) {
    asm volatile("ldmatrix.sync.aligned.m8n8.x4.shared.b16 {%0,%1,%2,%3}, [%4];"
                 : "=r"(r[0]), "=r"(r[1]), "=r"(r[2]), "=r"(r[3]) : "r"(addr));
}
__device__ __forceinline__ void ldsm_x4_trans(uint32_t* r, uint32_t addr) {
    asm volatile("ldmatrix.sync.aligned.m8n8.x4.trans.shared.b16 {%0,%1,%2,%3}, [%4];"
                 : "=r"(r[0]), "=r"(r[1]), "=r"(r[2]), "=r"(r[3]) : "r"(addr));
}
__device__ __forceinline__ void mma_f16(float* c, const uint32_t* a, const uint32_t* b) {
    asm volatile("mma.sync.aligned.m16n8k16.row.col.f32.f16.f16.f32 "
                 "{%0,%1,%2,%3}, {%4,%5,%6,%7}, {%8,%9}, {%0,%1,%2,%3};"
                 : "+f"(c[0]), "+f"(c[1]), "+f"(c[2]), "+f"(c[3])
                 : "r"(a[0]), "r"(a[1]), "r"(a[2]), "r"(a[3]), "r"(b[0]), "r"(b[1]));
}
// pack {lo=f0, hi=f1}
__device__ __forceinline__ uint32_t pack_f16x2(float f0, float f1) {
    uint32_t r;
    asm("cvt.rn.f16x2.f32 %0, %1, %2;" : "=r"(r) : "f"(f1), "f"(f0));
    return r;
}
__device__ __forceinline__ void cp_async16(uint32_t dst, const void* src) {
    asm volatile("cp.async.cg.shared.global [%0], [%1], 16;" :: "r"(dst), "l"(src));
}
#define CP_ASYNC_COMMIT() asm volatile("cp.async.commit_group;" ::: "memory")
#define CP_ASYNC_WAIT_1() asm volatile("cp.async.wait_group 1;" ::: "memory")
#define CP_ASYNC_WAIT_0() asm volatile("cp.async.wait_group 0;" ::: "memory")
#define SMEM_SWIZZLE_128B(o) ((o) ^ (((o) >> 3) & 0x70))

// ---------------------------------------------------------------------------
// Convert X -> fp16 hi/lo (same [m][k] layout).
// ---------------------------------------------------------------------------
__global__ __launch_bounds__(256) void convert_x_kernel(const float* __restrict__ X) {
    const int i = blockIdx.x * 256 + threadIdx.x;   // float4 index
    float4 v = ((const float4*)X)[i];
    float xs[4] = {v.x, v.y, v.z, v.w};
    union { __half h[4]; uint2 u; } hi, lo;
#pragma unroll
    for (int j = 0; j < 4; j++) {
        __half h = __float2half_rn(xs[j]);
        hi.h[j] = h;
        lo.h[j] = __float2half_rn(xs[j] - __half2float(h));
    }
    ((uint2*)g_xhi)[i] = hi.u;
    ((uint2*)g_xlo)[i] = lo.u;
}

// ---------------------------------------------------------------------------
// Convert + transpose W: [z][h][k][e] fp32 -> [z][h][e][k] fp16 single.
// ---------------------------------------------------------------------------
__global__ __launch_bounds__(256) void convert_w_kernel(
    const float* __restrict__ Wq, const float* __restrict__ Wk, const float* __restrict__ Wv) {
    const int zh = blockIdx.x;
    const int z = zh / NH, h = zh % NH;
    const float* __restrict__ W = (z == 0) ? Wq : (z == 1) ? Wk : Wv;
    const float* __restrict__ Wh = W + (size_t)h * DIN * DE;
    __half* __restrict__ o = g_wt + (size_t)zh * DE * DIN;
    for (int j = threadIdx.x; j < DE * DIN; j += 256) {
        const int e = j / DIN, k = j % DIN;
        o[j] = __float2half_rn(Wh[(size_t)k * DE + e]);
    }
}

// ---------------------------------------------------------------------------
// mma.sync QKV projection (fp16 2-term: xh*w + xl*w), cp.async
// double-buffered over 16 K-chunks of 64.
// CTA = 128 m-rows x 2 heads (128 n). 8 warps: 4m x 2n; warp tile 32m x 64n.
// Epilogue: Q fp16 hi/lo scaled by 0.125*log2e; K fp16; V fp16 hi/lo.
// Dynamic smem 96KB: 2 stages x (Xhi 16K | Xlo 16K | W 16K).
// ---------------------------------------------------------------------------
#define PSTAGE 49152
#define PROJ_SMEM (2 * PSTAGE)
#define QSCALE 0.1803368801112533f   // 0.125 * log2(e)

__global__ __launch_bounds__(256) void proj_mma_kernel() {
    extern __shared__ __align__(1024) char smem[];
    const uint32_t sb = smem_to_u32(smem);
    const int tid = threadIdx.x, w = tid >> 5, lane = tid & 31;
    const int wm = w & 3, wn = w >> 1 >> 1;      // wm 0..3, wn 0..1
    const int mt = blockIdx.x;                   // 0..63
    const int z  = blockIdx.y;                   // 0..2
    const int hg = blockIdx.z;                   // 0..7 (2 heads each)
    const int m0 = mt * 128;
    __half* __restrict__ ohi = (z == 0) ? g_qhi : (z == 1) ? g_khi : g_vhi;
    __half* __restrict__ olo = (z == 0) ? g_qlo : (z == 1) ? g_qlo : g_vlo;  // z=1 unused
    const float scale = (z == 0) ? QSCALE : 1.0f;

    float acc[2][8][4];
#pragma unroll
    for (int mi = 0; mi < 2; mi++)
#pragma unroll
        for (int ni = 0; ni < 8; ni++)
#pragma unroll
            for (int r = 0; r < 4; r++) acc[mi][ni][r] = 0.f;

    const int a_row = wm * 32 + (lane & 15);
    const int a_kb  = (lane >> 4) * 16;
    const int b_row = (lane & 7) + ((lane >> 4) << 3);
    const int b_kb  = ((lane >> 3) & 1) * 16;

    // --- cp.async chunk stager: Xhi | Xlo | W(2 heads) into stage buffer ---
    auto stage_chunk = [&](int c, int stg) {
        const uint32_t base = sb + stg * PSTAGE;
        const int k0 = c * 64;
#pragma unroll
        for (int it = 0; it < 4; it++) {
            const int j = it * 256 + tid;        // 0..1023
            const int r = j >> 3, g = j & 7;
            const uint32_t off = SMEM_SWIZZLE_128B((uint32_t)(r * 128 + g * 16));
            const size_t src = (size_t)(m0 + r) * DIN + k0 + g * 8;
            cp_async16(base + off,         g_xhi + src);
            cp_async16(base + 16384 + off, g_xlo + src);
        }
#pragma unroll
        for (int it = 0; it < 4; it++) {
            const int j = it * 256 + tid;        // 0..1023
            const int hidx = j >> 9;
            const int jj = j & 511, r = jj >> 3, g = jj & 7;
            const size_t src = ((size_t)((z * NH + hg * 2 + hidx) * DE + r)) * DIN + k0 + g * 8;
            const uint32_t off = hidx * 8192 + SMEM_SWIZZLE_128B((uint32_t)(r * 128 + g * 16));
            cp_async16(base + 32768 + off, g_wt + src);
        }
        CP_ASYNC_COMMIT();
    };

    stage_chunk(0, 0);

    for (int c = 0; c < 16; c++) {
        if (c + 1 < 16) {
            stage_chunk(c + 1, (c + 1) & 1);
            CP_ASYNC_WAIT_1();
        } else {
            CP_ASYNC_WAIT_0();
        }
        __syncthreads();   // chunk c visible; prior compute drained

        const uint32_t cb = sb + (c & 1) * PSTAGE;
        const uint32_t sxh = cb, sxl = cb + 16384, sw = cb + 32768;

#pragma unroll 1
        for (int ks = 0; ks < 4; ks++) {
            const int kso = ks * 32;
            uint32_t ahi[2][4], alo[2][4];
#pragma unroll
            for (int mi = 0; mi < 2; mi++) {
                const uint32_t off =
                    SMEM_SWIZZLE_128B((uint32_t)((a_row + mi * 16) * 128 + a_kb + kso));
                ldsm_x4(ahi[mi], sxh + off);
                ldsm_x4(alo[mi], sxl + off);
            }
            uint32_t bw[8][2];
#pragma unroll
            for (int nb = 0; nb < 4; nb++) {
                const uint32_t off = wn * 8192 +
                    SMEM_SWIZZLE_128B((uint32_t)((nb * 16 + b_row) * 128 + b_kb + kso));
                uint32_t t4[4];
                ldsm_x4(t4, sw + off);
                bw[2 * nb][0] = t4[0]; bw[2 * nb][1] = t4[1];
                bw[2 * nb + 1][0] = t4[2]; bw[2 * nb + 1][1] = t4[3];
            }
#pragma unroll
            for (int mi = 0; mi < 2; mi++)
#pragma unroll
                for (int ni = 0; ni < 8; ni++) {
                    mma_f16(acc[mi][ni], ahi[mi], bw[ni]);   // xh*w
                    mma_f16(acc[mi][ni], alo[mi], bw[ni]);   // xl*w
                }
        }
        __syncthreads();   // all reads of buffer c&1 done before it's restaged
    }

    const int h = hg * 2 + wn;
#pragma unroll
    for (int mi = 0; mi < 2; mi++) {
#pragma unroll
        for (int ni = 0; ni < 8; ni++) {
            const int e = ni * 8 + (lane & 3) * 2;
#pragma unroll
            for (int half = 0; half < 2; half++) {
                const int m = m0 + wm * 32 + mi * 16 + (lane >> 2) + half * 8;
                const int b = m / SEQ, s = m % SEQ;
                const float v0 = acc[mi][ni][half * 2] * scale;
                const float v1 = acc[mi][ni][half * 2 + 1] * scale;
                const uint32_t hp = pack_f16x2(v0, v1);
                const size_t off = ((size_t)((b * NH + h) * SEQ + s)) * DE + e;
                *(uint32_t*)(ohi + off) = hp;
                if (z != 1) {   // Q and V also store fp16 residuals
                    const __half2 hh = *reinterpret_cast<const __half2*>(&hp);
                    const float f00 = __low2float(hh), f01 = __high2float(hh);
                    *(uint32_t*)(olo + off) = pack_f16x2(v0 - f00, v1 - f01);
                }
            }
        }
    }
}

// ---------------------------------------------------------------------------
// mma.sync causal flash attention (fp16 2-term), cp.async double-buffered.
// Unchanged R16 winner.
// ---------------------------------------------------------------------------
#define ATTN_SMEM 49152

__global__ __launch_bounds__(256) void attn_mma_kernel(float* __restrict__ out)
{
    extern __shared__ __align__(1024) char asmem[];
    const uint32_t sb = smem_to_u32(asmem);

    const int qt = (gridDim.x - 1) - blockIdx.x;
    const int h  = blockIdx.y;
    const int b  = blockIdx.z;
    const int tid = threadIdx.x, w = tid >> 5, lane = tid & 31;
    const int ar = lane >> 2, ac = (lane & 3) * 2;

    const size_t bh = (size_t)(b * NH + h) * SEQ * DE;
    const __half* __restrict__ Qhi = g_qhi + bh;
    const __half* __restrict__ Qlo = g_qlo + bh;
    const __half* srcs[3] = {g_khi + bh, g_vhi + bh, g_vlo + bh};

    const int q0 = qt * 128 + w * 16;        // warp's first q-row

    // Q fragments (hi/lo), 4 k-steps of 16 over e=64.
    uint32_t qh[4][4], ql[4][4];
#pragma unroll
    for (int ks = 0; ks < 4; ks++) {
        const int r0 = q0 + ar, r1 = r0 + 8;
        const int c0 = ks * 16 + ac, c1 = c0 + 8;
        qh[ks][0] = *(const uint32_t*)(Qhi + (size_t)r0 * DE + c0);
        qh[ks][1] = *(const uint32_t*)(Qhi + (size_t)r1 * DE + c0);
        qh[ks][2] = *(const uint32_t*)(Qhi + (size_t)r0 * DE + c1);
        qh[ks][3] = *(const uint32_t*)(Qhi + (size_t)r1 * DE + c1);
        ql[ks][0] = *(const uint32_t*)(Qlo + (size_t)r0 * DE + c0);
        ql[ks][1] = *(const uint32_t*)(Qlo + (size_t)r1 * DE + c0);
        ql[ks][2] = *(const uint32_t*)(Qlo + (size_t)r0 * DE + c1);
        ql[ks][3] = *(const uint32_t*)(Qlo + (size_t)r1 * DE + c1);
    }

    float O[8][4];
#pragma unroll
    for (int et = 0; et < 8; et++)
#pragma unroll
        for (int r = 0; r < 4; r++) O[et][r] = 0.f;
    float m0r = -1e30f, m1r = -1e30f, l0r = 0.f, l1r = 0.f;

    const int lj = lane >> 3, l7 = lane & 7;
    const int nkt = 2 * qt + 2;

    // --- cp.async tile stager: 3 regions x 8KB into stage buffer ---
    auto stage_tile = [&](int kt, int stg) {
        const uint32_t base = sb + stg * 24576;
#pragma unroll
        for (int u = 0; u < 6; u++) {
            const int j = ((u & 1) << 8) + tid;      // 0..511
            const int r = j >> 3, g = j & 7;
            const uint32_t off = SMEM_SWIZZLE_128B((uint32_t)(r * 128 + g * 16));
            const size_t src = (size_t)(kt * 64 + r) * DE + g * 8;
            cp_async16(base + (u >> 1) * 8192 + off, srcs[u >> 1] + src);
        }
        CP_ASYNC_COMMIT();
    };

    stage_tile(0, 0);

    for (int kt = 0; kt < nkt; kt++) {
        if (kt + 1 < nkt) {
            stage_tile(kt + 1, (kt + 1) & 1);
            CP_ASYNC_WAIT_1();
        } else {
            CP_ASYNC_WAIT_0();
        }
        __syncthreads();   // tile kt visible to all; prior compute drained

        if (kt * 64 <= q0 + 15) {
            const uint32_t cb = sb + (kt & 1) * 24576;
            const uint32_t sk = cb, svh = cb + 8192, svl = cb + 16384;

            // ---- S = Q K^T over this 64-key tile (2-term fp16) ----
            float S[8][4];
#pragma unroll
            for (int nt = 0; nt < 8; nt++)
#pragma unroll
                for (int r = 0; r < 4; r++) S[nt][r] = 0.f;

#pragma unroll 1
            for (int ks = 0; ks < 4; ks++) {
#pragma unroll
                for (int ntp = 0; ntp < 4; ntp++) {
                    const int krow = ntp * 16 + ((lj >> 1) << 3) + l7;
                    const uint32_t off =
                        SMEM_SWIZZLE_128B((uint32_t)(krow * 128 + (lj & 1) * 16 + ks * 32));
                    uint32_t th[4];
                    ldsm_x4(th, sk + off);
                    mma_f16(S[2 * ntp],     qh[ks], th + 0);
                    mma_f16(S[2 * ntp],     ql[ks], th + 0);
                    mma_f16(S[2 * ntp + 1], qh[ks], th + 2);
                    mma_f16(S[2 * ntp + 1], ql[ks], th + 2);
                }
            }

            // ---- causal mask (diagonal band only) ----
            const int r0g = q0 + ar, r1g = r0g + 8;
            if (kt * 64 + 63 > q0) {
#pragma unroll
                for (int nt = 0; nt < 8; nt++) {
                    const int cbn = kt * 64 + nt * 8 + ac;
                    if (cbn     > r0g) S[nt][0] = -1e30f;
                    if (cbn + 1 > r0g) S[nt][1] = -1e30f;
                    if (cbn     > r1g) S[nt][2] = -1e30f;
                    if (cbn + 1 > r1g) S[nt][3] = -1e30f;
                }
            }

            // ---- online softmax (exp2 domain) ----
            float mc0 = -1e30f, mc1 = -1e30f;
#pragma unroll
            for (int nt = 0; nt < 8; nt++) {
                mc0 = fmaxf(mc0, fmaxf(S[nt][0], S[nt][1]));
                mc1 = fmaxf(mc1, fmaxf(S[nt][2], S[nt][3]));
            }
            mc0 = fmaxf(mc0, __shfl_xor_sync(0xffffffffu, mc0, 1));
            mc0 = fmaxf(mc0, __shfl_xor_sync(0xffffffffu, mc0, 2));
            mc1 = fmaxf(mc1, __shfl_xor_sync(0xffffffffu, mc1, 1));
            mc1 = fmaxf(mc1, __shfl_xor_sync(0xffffffffu, mc1, 2));

            const float mn0 = fmaxf(m0r, mc0), mn1 = fmaxf(m1r, mc1);
            if (__any_sync(0xffffffffu, (mn0 > m0r) || (mn1 > m1r))) {
                const float cr0 = exp2f(m0r - mn0), cr1 = exp2f(m1r - mn1);
                m0r = mn0; m1r = mn1;
                l0r *= cr0; l1r *= cr1;
#pragma unroll
                for (int et = 0; et < 8; et++) {
                    O[et][0] *= cr0; O[et][1] *= cr0;
                    O[et][2] *= cr1; O[et][3] *= cr1;
                }
            }

            float rs0 = 0.f, rs1 = 0.f;
#pragma unroll
            for (int nt = 0; nt < 8; nt++) {
                S[nt][0] = exp2f(S[nt][0] - m0r);
                S[nt][1] = exp2f(S[nt][1] - m0r);
                S[nt][2] = exp2f(S[nt][2] - m1r);
                S[nt][3] = exp2f(S[nt][3] - m1r);
                rs0 += S[nt][0] + S[nt][1];
                rs1 += S[nt][2] + S[nt][3];
            }
            rs0 += __shfl_xor_sync(0xffffffffu, rs0, 1);
            rs0 += __shfl_xor_sync(0xffffffffu, rs0, 2);
            rs1 += __shfl_xor_sync(0xffffffffu, rs1, 1);
            rs1 += __shfl_xor_sync(0xffffffffu, rs1, 2);
            l0r += rs0; l1r += rs1;

            // ---- O += P V (2-term fp16: P*Vh + P*Vl) ----
#pragma unroll 1
            for (int kks = 0; kks < 4; kks++) {
                uint32_t ah[4];
#pragma unroll
                for (int q2 = 0; q2 < 2; q2++) {
                    const int nt = 2 * kks + q2;
                    ah[2 * q2]     = pack_f16x2(S[nt][0], S[nt][1]);
                    ah[2 * q2 + 1] = pack_f16x2(S[nt][2], S[nt][3]);
                }
#pragma unroll
                for (int etp = 0; etp < 4; etp++) {
                    const int krow = kks * 16 + ((lj & 1) << 3) + l7;
                    const uint32_t off =
                        SMEM_SWIZZLE_128B((uint32_t)(krow * 128 + etp * 32 + (lj >> 1) * 16));
                    uint32_t tvh[4], tvl[4];
                    ldsm_x4_trans(tvh, svh + off);
                    ldsm_x4_trans(tvl, svl + off);
                    mma_f16(O[2 * etp],     ah, tvh + 0);
                    mma_f16(O[2 * etp],     ah, tvl + 0);
                    mma_f16(O[2 * etp + 1], ah, tvh + 2);
                    mma_f16(O[2 * etp + 1], ah, tvl + 2);
                }
            }
        }

        __syncthreads();   // all reads of buffer kt&1 done before it's restaged
    }

    // ---- finalize + store ----
    const float i0 = 1.f / l0r, i1 = 1.f / l1r;
    const int row0 = qt * 128 + w * 16 + ar;
    const size_t ob0 = (size_t)(b * SEQ + row0) * (NH * DE) + h * DE;
    const size_t ob1 = (size_t)(b * SEQ + row0 + 8) * (NH * DE) + h * DE;
#pragma unroll
    for (int et = 0; et < 8; et++) {
        const int e = et * 8 + ac;
        *(float2*)(out + ob0 + e) = make_float2(O[et][0] * i0, O[et][1] * i0);
        *(float2*)(out + ob1 + e) = make_float2(O[et][2] * i1, O[et][3] * i1);
    }
}

// ---------------------------------------------------------------------------
extern "C" void kernel_launch(void* const* d_in, const int* in_sizes, int n_in,
                              void* d_out, int out_size) {
    (void)in_sizes; (void)n_in; (void)out_size;
    const float* X  = (const float*)d_in[0];
    const float* Wq = (const float*)d_in[1];
    const float* Wk = (const float*)d_in[2];
    const float* Wv = (const float*)d_in[3];
    float* out = (float*)d_out;

    cudaFuncSetAttribute(proj_mma_kernel,
                         cudaFuncAttributeMaxDynamicSharedMemorySize, PROJ_SMEM);
    cudaFuncSetAttribute(attn_mma_kernel,
                         cudaFuncAttributeMaxDynamicSharedMemorySize, ATTN_SMEM);

    convert_x_kernel<<<(MROWS * DIN / 4) / 256, 256>>>(X);
    convert_w_kernel<<<3 * NH, 256>>>(Wq, Wk, Wv);

    dim3 gp(64, 3, 8);
    proj_mma_kernel<<<gp, 256, PROJ_SMEM>>>();

    dim3 ga(SEQ / 128, NH, BATCH);
    attn_mma_kernel<<<ga, 256, ATTN_SMEM>>>(out);
}